// round 11
// baseline (speedup 1.0000x reference)
#include <cuda_runtime.h>
#include <cuda_bf16.h>
#include <cstdint>
#include <math.h>

#define VOCAB 32000
#define EMB   256
#define UNITS 1024
#define NB    64
#define NT    256
#define G3    3072
#define REC_BLOCKS 128
#define FINBUF (NT % 3)   // buffer holding final h (h_256) = 1

typedef unsigned long long ull;

// ---------------- device scratch ---------------------------------------------------
__device__ float g_gx[(size_t)2 * NT * NB * G3];         // packed gate-major inputs
__device__ __nv_bfloat16 g_ubfT[2][2][G3][UNITS];        // [split][dir][p][k] U^T hi/lo
__device__ ull  g_wbfF[2 * 16 * 384 * 64];               // W frags [dir][ks][pt][lane][sp]
__device__ __nv_bfloat16 g_embbf[2][VOCAB][EMB];         // emb hi/lo
__device__ float g_h [2][3][NB][UNITS];                  // fp32 h, [dir][buf][b][u], mod-3
__device__ __nv_bfloat16 g_hbf[2][2][3][NB][UNITS];      // [split][dir][buf][b][u]
__device__ unsigned char g_mask[2][NT][NB];
__device__ unsigned g_bar_count;
__device__ unsigned g_bar_gen;
__device__ unsigned g_gflag[2][16];                      // per-dir chunk-group step flags

// ---------------- helpers -----------------------------------------------------------
__device__ __forceinline__ uint32_t smem_u32(const void* p) {
    uint32_t a;
    asm("{ .reg .u64 t; cvta.to.shared.u64 t, %1; cvt.u32.u64 %0, t; }" : "=r"(a) : "l"(p));
    return a;
}
__device__ __forceinline__ unsigned short bfbits(__nv_bfloat16 v) {
    return *(unsigned short*)&v;
}

#define CP_ASYNC16(dst, src) \
    asm volatile("cp.async.cg.shared.global [%0], [%1], 16;" :: "r"(dst), "l"(src) : "memory")
#define CP_COMMIT() asm volatile("cp.async.commit_group;" ::: "memory")
#define CP_WAIT0()  asm volatile("cp.async.wait_group 0;" ::: "memory")

#define LDMATRIX_X4(r0, r1, r2, r3, addr) \
    asm volatile("ldmatrix.sync.aligned.m8n8.x4.shared.b16 {%0,%1,%2,%3}, [%4];" \
                 : "=r"(r0), "=r"(r1), "=r"(r2), "=r"(r3) : "r"(addr))

#define MMA_BF16(c, a0, a1, a2, a3, b0, b1) \
    asm volatile("mma.sync.aligned.m16n8k16.row.col.f32.bf16.bf16.f32 " \
                 "{%0,%1,%2,%3}, {%4,%5,%6,%7}, {%8,%9}, {%0,%1,%2,%3};" \
                 : "+f"((c)[0]), "+f"((c)[1]), "+f"((c)[2]), "+f"((c)[3]) \
                 : "r"(a0), "r"(a1), "r"(a2), "r"(a3), "r"(b0), "r"(b1))

__device__ __forceinline__ void wait_flag(const unsigned* f, unsigned need) {
    unsigned v;
    do {
        asm volatile("ld.acquire.gpu.u32 %0, [%1];" : "=r"(v) : "l"(f) : "memory");
    } while (v < need);
}

__device__ __forceinline__ void barrier_generic(unsigned* cnt, unsigned* gen,
                                                unsigned nblk, unsigned target) {
    __syncthreads();
    if (threadIdx.x == 0) {
        unsigned prev;
        asm volatile("atom.acq_rel.gpu.add.u32 %0, [%1], 1;"
                     : "=r"(prev) : "l"(cnt) : "memory");
        if (prev == target * nblk - 1u) {
            asm volatile("st.release.gpu.u32 [%0], %1;"
                         :: "l"(gen), "r"(target) : "memory");
        } else {
            unsigned g;
            do {
                asm volatile("ld.acquire.gpu.u32 %0, [%1];"
                             : "=r"(g) : "l"(gen) : "memory");
            } while (g < target);
        }
    }
    __syncthreads();
}

// ---------------- prep ---------------------------------------------------------------
__global__ void prep_kernel(const int* __restrict__ x, const float* __restrict__ hidden,
                            const float* __restrict__ emb,
                            const float* __restrict__ Wf, const float* __restrict__ Uf,
                            const float* __restrict__ Wb, const float* __restrict__ Ub) {
    const long long NUBF = 2LL * 2 * G3 * UNITS;          // U^T hi/lo
    const long long NWF  = 2LL * 16 * 384 * 64;           // W frags
    const long long NEMB = 2LL * VOCAB * EMB;             // emb hi/lo
    const long long NM   = 2LL * NT * NB;
    const long long NH   = 2LL * NB * UNITS;
    const long long NHBF = 2LL * 2 * NB * UNITS;
    const long long total = NUBF + NWF + NEMB + NM + NH + NHBF;
    const long long stride = (long long)gridDim.x * blockDim.x;
    for (long long i = (long long)blockIdx.x * blockDim.x + threadIdx.x; i < total; i += stride) {
        if (i < NUBF) {
            int split = (int)(i / (2LL * G3 * UNITS));
            long long r1 = i - (long long)split * 2 * G3 * UNITS;
            int dir = (int)(r1 / ((long long)G3 * UNITS));
            long long r2 = r1 - (long long)dir * G3 * UNITS;
            int p = (int)(r2 / UNITS);
            int k = (int)(r2 % UNITS);
            const float* U = dir ? Ub : Uf;
            float val = U[(long long)k * G3 + (p % 3) * UNITS + p / 3];
            __nv_bfloat16 hi = __float2bfloat16(val);
            if (split == 0) g_ubfT[0][dir][p][k] = hi;
            else            g_ubfT[1][dir][p][k] = __float2bfloat16(val - __bfloat162float(hi));
        } else if (i < NUBF + NWF) {
            long long j = i - NUBF;
            int dir = (int)(j / (16LL * 384 * 64));
            int r = (int)(j % (16LL * 384 * 64));
            int ks = r / (384 * 64); r %= 384 * 64;
            int pt = r / 64; r %= 64;
            int lane = r >> 1;
            int sp = r & 1;
            int gid = lane >> 2, tig = lane & 3;
            int p = pt * 8 + gid;
            const float* W = dir ? Wb : Wf;
            const long long poff = (long long)(p % 3) * UNITS + p / 3;
            int k0 = ks * 16 + 2 * tig;
            float v0 = W[(long long)(k0 + 0) * G3 + poff];
            float v1 = W[(long long)(k0 + 1) * G3 + poff];
            float v2 = W[(long long)(k0 + 8) * G3 + poff];
            float v3 = W[(long long)(k0 + 9) * G3 + poff];
            unsigned short b0, b1, b2, b3;
            if (sp == 0) {
                b0 = bfbits(__float2bfloat16(v0)); b1 = bfbits(__float2bfloat16(v1));
                b2 = bfbits(__float2bfloat16(v2)); b3 = bfbits(__float2bfloat16(v3));
            } else {
                __nv_bfloat16 h0 = __float2bfloat16(v0), h1 = __float2bfloat16(v1);
                __nv_bfloat16 h2 = __float2bfloat16(v2), h3 = __float2bfloat16(v3);
                b0 = bfbits(__float2bfloat16(v0 - __bfloat162float(h0)));
                b1 = bfbits(__float2bfloat16(v1 - __bfloat162float(h1)));
                b2 = bfbits(__float2bfloat16(v2 - __bfloat162float(h2)));
                b3 = bfbits(__float2bfloat16(v3 - __bfloat162float(h3)));
            }
            g_wbfF[j] = (ull)b0 | ((ull)b1 << 16) | ((ull)b2 << 32) | ((ull)b3 << 48);
        } else if (i < NUBF + NWF + NEMB) {
            long long j = i - NUBF - NWF;
            int sp = (int)(j / ((long long)VOCAB * EMB));
            long long rem = j - (long long)sp * VOCAB * EMB;
            int e = (int)(rem / EMB), c = (int)(rem % EMB);
            float val = emb[(long long)e * EMB + c];
            __nv_bfloat16 hi = __float2bfloat16(val);
            if (sp == 0) g_embbf[0][e][c] = hi;
            else         g_embbf[1][e][c] = __float2bfloat16(val - __bfloat162float(hi));
        } else if (i < NUBF + NWF + NEMB + NM) {
            long long j = i - NUBF - NWF - NEMB;
            int dir = (int)(j / (NT * NB));
            int rem = (int)(j % (NT * NB));
            int s = rem / NB, b = rem % NB;
            int t = dir ? (NT - 1 - s) : s;
            g_mask[dir][s][b] = (x[b * NT + t] != 0) ? 1 : 0;
        } else if (i < NUBF + NWF + NEMB + NM + NH) {
            long long j = i - NUBF - NWF - NEMB - NM;
            int dir = (int)(j / (NB * UNITS));
            int rem = (int)(j % (NB * UNITS));
            int b = rem / UNITS, u = rem % UNITS;
            g_h[dir][0][b][u] = hidden[b * UNITS + u];
        } else {
            long long j = i - NUBF - NWF - NEMB - NM - NH;
            int split = (int)(j / (2LL * NB * UNITS));
            long long r1 = j - (long long)split * 2 * NB * UNITS;
            int dir = (int)(r1 / (NB * UNITS));
            int rem = (int)(r1 % (NB * UNITS));
            int b = rem / UNITS, u = rem % UNITS;
            float val = hidden[b * UNITS + u];
            __nv_bfloat16 hi = __float2bfloat16(val);
            if (split == 0) g_hbf[0][dir][0][b][u] = hi;
            else            g_hbf[1][dir][0][b][u] = __float2bfloat16(val - __bfloat162float(hi));
        }
    }
    if (blockIdx.x == 0 && threadIdx.x < 32) {
        g_gflag[threadIdx.x >> 4][threadIdx.x & 15] = 0u;
        if (threadIdx.x == 0) { g_bar_count = 0u; g_bar_gen = 0u; }
    }
}

// ---------------- gx via HMMA: C[64x64] = xe[64x256] @ W[64x256]^T, 3-term split ----
#define GX_SMEM_BYTES (65536 + 512)
__global__ __launch_bounds__(256) void gx_kernel(const int* __restrict__ x,
                                                 const float* __restrict__ bf_in,
                                                 const float* __restrict__ bb_in) {
    extern __shared__ char smx[];
    const uint32_t smb = smem_u32(smx);
    int* toks = (int*)(smx + 65536);

    const int ct  = blockIdx.x;
    const int t   = blockIdx.y;
    const int dir = blockIdx.z;
    const int tid = threadIdx.x;
    const int wid = tid >> 5;
    const int lane = tid & 31;
    const int mi = wid & 3;
    const int nj = wid >> 2;
    const int gid = lane >> 2;
    const int tig = lane & 3;

    if (tid < 64) {
        int tt = dir ? (NT - 1 - t) : t;
        toks[tid] = x[tid * NT + tt];
    }
    __syncthreads();

    // stage A (xe hi/lo), swizzled 16B granules in 512B rows
#pragma unroll
    for (int j = 0; j < 16; j++) {
        int f = tid + j * 256;
        int sp = f >> 11;
        int rem = f & 2047;
        int row = rem >> 5;
        int seg = rem & 31;
        const void* src = &g_embbf[sp][toks[row]][seg * 8];
        uint32_t dst = smb + (uint32_t)sp * 32768u + (uint32_t)(row * 512)
                     + (uint32_t)((seg ^ (row & 7)) << 4);
        CP_ASYNC16(dst, src);
    }
    CP_COMMIT();
    CP_WAIT0();
    __syncthreads();

    float c[4][4];
#pragma unroll
    for (int i = 0; i < 4; i++) { c[i][0] = 0.f; c[i][1] = 0.f; c[i][2] = 0.f; c[i][3] = 0.f; }

    const int arow = mi * 16 + (lane & 15);
    const int acb  = lane >> 4;
    const uint32_t abase = smb + (uint32_t)(arow * 512);
    const ull* wf = g_wbfF + (size_t)dir * 16 * 384 * 64;

#pragma unroll
    for (int ks = 0; ks < 16; ks++) {
        const int seg = ks * 2 + acb;
        const uint32_t sw = (uint32_t)((seg ^ (arow & 7)) << 4);
        uint32_t ah0, ah1, ah2, ah3, al0, al1, al2, al3;
        LDMATRIX_X4(ah0, ah1, ah2, ah3, abase + sw);
        LDMATRIX_X4(al0, al1, al2, al3, abase + 32768u + sw);
        ull vh[4], vl[4];
#pragma unroll
        for (int ntl = 0; ntl < 4; ntl++) {
            size_t base = ((size_t)ks * 384 + ct * 8 + nj * 4 + ntl) * 64 + lane * 2;
            ulonglong2 v = __ldg((const ulonglong2*)(wf + base));
            vh[ntl] = v.x;
            vl[ntl] = v.y;
        }
#pragma unroll
        for (int ntl = 0; ntl < 4; ntl++)
            MMA_BF16(c[ntl], ah0, ah1, ah2, ah3, (uint32_t)vh[ntl], (uint32_t)(vh[ntl] >> 32));
#pragma unroll
        for (int ntl = 0; ntl < 4; ntl++)
            MMA_BF16(c[ntl], al0, al1, al2, al3, (uint32_t)vh[ntl], (uint32_t)(vh[ntl] >> 32));
#pragma unroll
        for (int ntl = 0; ntl < 4; ntl++)
            MMA_BF16(c[ntl], ah0, ah1, ah2, ah3, (uint32_t)vl[ntl], (uint32_t)(vl[ntl] >> 32));
    }

    // redistribute C through smem
    __syncthreads();
    float* Cb = (float*)smx;              // [64][68]
    {
        const int r0 = mi * 16 + gid;
#pragma unroll
        for (int ntl = 0; ntl < 4; ntl++) {
            const int col = nj * 32 + ntl * 8 + 2 * tig;
            *(float2*)&Cb[r0 * 68 + col]       = make_float2(c[ntl][0], c[ntl][1]);
            *(float2*)&Cb[(r0 + 8) * 68 + col] = make_float2(c[ntl][2], c[ntl][3]);
        }
    }
    __syncthreads();

    // epilogue: + b_in, write packed gx
    {
        const int b   = tid & 63;
        const int grp = tid >> 6;
        const int pbase = ct * 64;
        const float* bsrc = dir ? bb_in : bf_in;
        float o[16];
#pragma unroll
        for (int q = 0; q < 16; q++) {
            int p = pbase + grp * 16 + q;
            o[q] = Cb[b * 68 + grp * 16 + q] + __ldg(bsrc + (p % 3) * UNITS + p / 3);
        }
        float* gxp = g_gx + ((size_t)(dir * NT + t) * NB + b) * G3 + pbase + grp * 16;
#pragma unroll
        for (int q = 0; q < 4; q++)
            *(float4*)(gxp + q * 4) = *(const float4*)&o[q * 4];
    }
}

// ---------------- persistent HMMA recurrent kernel -----------------------------------
// Flag-based producer/consumer sync, 3 rotating h buffers, no per-step grid barrier.
#define ABUF_OFF    196608u
#define BIAS_OFF    229376u
#define REC_SMEM_BYTES 229568

__global__ __launch_bounds__(256, 1) void recurrent_kernel(const float* __restrict__ bf_rec,
                                                           const float* __restrict__ bb_rec,
                                                           const float* __restrict__ Wp,
                                                           const float* __restrict__ bp,
                                                           float* __restrict__ out) {
    extern __shared__ char smx[];
    const uint32_t smb = smem_u32(smx);

    const int blk   = blockIdx.x;
    const int dir   = blk >> 6;
    const int utile = blk & 63;
    const int pbase = utile * 48;
    const int ubase = utile * 16;
    const int tid  = threadIdx.x;
    const int wid  = tid >> 5;
    const int lane = tid & 31;
    const int mi = wid & 3;
    const int nj = wid >> 2;
    const int gid = lane >> 2;
    const int tig = lane & 3;

    if (tid < 48) {
        const float* brec = dir ? bb_rec : bf_rec;
        ((float*)(smx + BIAS_OFF))[tid] = brec[(tid % 3) * UNITS + ubase + tid / 3];
    }

    // fragment-ordered U in smem, hi/lo PAIRED in 16B: [pair = ksg*6 + ntile][lane]
    for (int e = wid; e < 384; e += 8) {
        int ks = e / 6;
        int nt = e % 6;
        int p  = pbase + nt * 8 + gid;
        const __nv_bfloat16* uh = &g_ubfT[0][dir][p][ks * 16 + 2 * tig];
        const __nv_bfloat16* ul = &g_ubfT[1][dir][p][ks * 16 + 2 * tig];
        ulonglong2 v;
        v.x = (ull)(*(const uint32_t*)uh) | ((ull)(*(const uint32_t*)(uh + 8)) << 32);
        v.y = (ull)(*(const uint32_t*)ul) | ((ull)(*(const uint32_t*)(ul + 8)) << 32);
        *(ulonglong2*)(smx + ((size_t)e * 32 + lane) * 16) = v;
    }
    __syncthreads();

    const int b_ep = tid & 63;
    const int usub = tid >> 6;
    unsigned* myflag = &g_gflag[dir][utile >> 2];

    int pp = 0;
    for (int s = 0; s < NT; s++) {
        const int ppn = (pp == 2) ? 0 : pp + 1;
        const unsigned need = 4u * (unsigned)s;

        float gxv[12];
        {
            const float* gxr = g_gx + ((size_t)(dir * NT + s) * NB + b_ep) * G3 + pbase + usub * 12;
#pragma unroll
            for (int q = 0; q < 3; q++)
                *(float4*)&gxv[q * 4] = __ldcs((const float4*)(gxr + q * 4));
        }
        float hp[4];
        *(float4*)hp = __ldcg((const float4*)(&g_h[dir][pp][b_ep][ubase + usub * 4]));
        const int m = g_mask[dir][s][b_ep];

        // wait producers of chunk 0, then stage it
        wait_flag(&g_gflag[dir][0], need);
        {
#pragma unroll
            for (int j = 0; j < 4; j++) {
                int f = tid + j * 256;
                int sp = f >> 9, row = (f >> 3) & 63, seg = f & 7;
                const void* src = &g_hbf[sp][dir][pp][row][seg * 8];
                uint32_t dst = smb + ABUF_OFF + (uint32_t)sp * 8192u
                             + (uint32_t)(row * 128) + (uint32_t)((seg ^ (row & 7)) * 16);
                CP_ASYNC16(dst, src);
            }
            CP_COMMIT();
        }

        float c[3][4];
#pragma unroll
        for (int i = 0; i < 3; i++) { c[i][0] = 0.f; c[i][1] = 0.f; c[i][2] = 0.f; c[i][3] = 0.f; }

        const int arow = mi * 16 + (lane & 15);
        const int acb  = lane >> 4;

        for (int ci = 0; ci < 16; ci++) {
            CP_WAIT0();
            __syncthreads();
            if (ci < 15) {
                wait_flag(&g_gflag[dir][ci + 1], need);
                const int slot = (ci + 1) & 1;
#pragma unroll
                for (int j = 0; j < 4; j++) {
                    int f = tid + j * 256;
                    int sp = f >> 9, row = (f >> 3) & 63, seg = f & 7;
                    const void* src = &g_hbf[sp][dir][pp][row][(ci + 1) * 64 + seg * 8];
                    uint32_t dst = smb + ABUF_OFF + (uint32_t)slot * 16384u + (uint32_t)sp * 8192u
                                 + (uint32_t)(row * 128) + (uint32_t)((seg ^ (row & 7)) * 16);
                    CP_ASYNC16(dst, src);
                }
                CP_COMMIT();
            }
            const uint32_t abase = smb + ABUF_OFF + (uint32_t)(ci & 1) * 16384u
                                 + (uint32_t)(arow * 128);
#pragma unroll
            for (int ks = 0; ks < 4; ks++) {
                const int seg = ks * 2 + acb;
                const uint32_t sw = (uint32_t)((seg ^ (arow & 7)) * 16);
                uint32_t ah0, ah1, ah2, ah3, al0, al1, al2, al3;
                LDMATRIX_X4(ah0, ah1, ah2, ah3, abase + sw);
                LDMATRIX_X4(al0, al1, al2, al3, abase + 8192u + sw);
                const int ksg = ci * 4 + ks;
                ull vh[3], vl[3];
#pragma unroll
                for (int ntl = 0; ntl < 3; ntl++) {
                    ulonglong2 v = *(const ulonglong2*)
                        (smx + ((size_t)(ksg * 6 + nj * 3 + ntl) * 32 + lane) * 16);
                    vh[ntl] = v.x;
                    vl[ntl] = v.y;
                }
#pragma unroll
                for (int ntl = 0; ntl < 3; ntl++)
                    MMA_BF16(c[ntl], ah0, ah1, ah2, ah3, (uint32_t)vh[ntl], (uint32_t)(vh[ntl] >> 32));
#pragma unroll
                for (int ntl = 0; ntl < 3; ntl++)
                    MMA_BF16(c[ntl], al0, al1, al2, al3, (uint32_t)vh[ntl], (uint32_t)(vh[ntl] >> 32));
#pragma unroll
                for (int ntl = 0; ntl < 3; ntl++)
                    MMA_BF16(c[ntl], ah0, ah1, ah2, ah3, (uint32_t)vl[ntl], (uint32_t)(vl[ntl] >> 32));
            }
        }

        // redistribute C through smem
        __syncthreads();
        float* Cb = (float*)(smx + ABUF_OFF);
        {
            const int r0 = mi * 16 + gid;
#pragma unroll
            for (int ntl = 0; ntl < 3; ntl++) {
                const int col = nj * 24 + ntl * 8 + 2 * tig;
                *(float2*)&Cb[r0 * 52 + col]       = make_float2(c[ntl][0], c[ntl][1]);
                *(float2*)&Cb[(r0 + 8) * 52 + col] = make_float2(c[ntl][2], c[ntl][3]);
            }
        }
        __syncthreads();

        // GRU epilogue
        {
            float acc[12];
#pragma unroll
            for (int q = 0; q < 3; q++)
                *(float4*)&acc[q * 4] = *(const float4*)&Cb[b_ep * 52 + usub * 12 + q * 4];
            const float* sb = (const float*)(smx + BIAS_OFF) + usub * 12;
            const int tt = dir ? (NT - 1 - s) : s;

            float hn[4];
            __nv_bfloat16 hi4[4], lo4[4];
#pragma unroll
            for (int ul = 0; ul < 4; ul++) {
                float z = 1.f / (1.f + expf(-(gxv[ul * 3 + 0] + acc[ul * 3 + 0] + sb[ul * 3 + 0])));
                float r = 1.f / (1.f + expf(-(gxv[ul * 3 + 1] + acc[ul * 3 + 1] + sb[ul * 3 + 1])));
                float hh = tanhf(gxv[ul * 3 + 2] + r * (acc[ul * 3 + 2] + sb[ul * 3 + 2]));
                float v = z * hp[ul] + (1.f - z) * hh;
                if (!m) v = hp[ul];
                hn[ul] = v;
                __nv_bfloat16 hi = __float2bfloat16(v);
                hi4[ul] = hi;
                lo4[ul] = __float2bfloat16(v - __bfloat162float(hi));
            }
            const int uo = ubase + usub * 4;
            *(float4*)(out + ((size_t)b_ep * NT + tt) * (2 * UNITS) + dir * UNITS + uo)
                = *(const float4*)hn;
            *(float4*)(&g_h[dir][ppn][b_ep][uo]) = *(const float4*)hn;
            *(uint2*)(&g_hbf[0][dir][ppn][b_ep][uo]) = *(const uint2*)hi4;
            *(uint2*)(&g_hbf[1][dir][ppn][b_ep][uo]) = *(const uint2*)lo4;
        }

        __syncthreads();
        if (tid == 0)
            asm volatile("red.release.gpu.add.u32 [%0], %1;" :: "l"(myflag), "r"(1u) : "memory");
        pp = ppn;
    }

    // full barrier before cross-dir final state
    barrier_generic(&g_bar_count, &g_bar_gen, 128u, 1u);

    // fused final state: tanh(concat(hf,hb) @ Wp + bp), final h in buffer FINBUF
    {
        float* sst = (float*)smx;
        const int tx8 = tid & 7;
        const int tyS = tid >> 3;
        const int b0 = tyS * 2;
        const int ocol = blk * 8 + tx8;
        const float* wp = Wp + ocol;
        float acc0 = 0.f, acc1 = 0.f;
        for (int k0 = 0; k0 < 2 * UNITS; k0 += 128) {
            __syncthreads();
#pragma unroll
            for (int j = 0; j < 8; j++) {
                int f = tid + j * 256;
                int b = f >> 5;
                int k4 = (f & 31) << 2;
                int gk = k0 + k4;
                float4 v = __ldcg((const float4*)(&g_h[gk >> 10][FINBUF][b][gk & 1023]));
                *(float4*)&sst[b * 132 + k4] = v;
            }
            __syncthreads();
#pragma unroll 8
            for (int kk = 0; kk < 128; kk++) {
                float w = __ldg(wp + (size_t)(k0 + kk) * UNITS);
                acc0 = fmaf(sst[b0 * 132 + kk], w, acc0);
                acc1 = fmaf(sst[(b0 + 1) * 132 + kk], w, acc1);
            }
        }
        float bpv = bp[ocol];
        const size_t so = (size_t)NB * NT * (2 * UNITS);
        out[so + (size_t)b0 * UNITS + ocol]       = tanhf(acc0 + bpv);
        out[so + (size_t)(b0 + 1) * UNITS + ocol] = tanhf(acc1 + bpv);
    }
}

// ---------------- launch --------------------------------------------------------------
extern "C" void kernel_launch(void* const* d_in, const int* in_sizes, int n_in,
                              void* d_out, int out_size) {
    (void)in_sizes; (void)n_in; (void)out_size;
    const int*   x      = (const int*)  d_in[0];
    const float* hidden = (const float*)d_in[1];
    const float* emb    = (const float*)d_in[2];
    const float* Wf     = (const float*)d_in[3];
    const float* Uf     = (const float*)d_in[4];
    const float* bf_in  = (const float*)d_in[5];
    const float* bf_rec = (const float*)d_in[6];
    const float* Wb     = (const float*)d_in[7];
    const float* Ub     = (const float*)d_in[8];
    const float* bb_in  = (const float*)d_in[9];
    const float* bb_rec = (const float*)d_in[10];
    const float* Wp     = (const float*)d_in[11];
    const float* bp     = (const float*)d_in[12];
    float* out = (float*)d_out;

    cudaFuncSetAttribute(recurrent_kernel,
                         cudaFuncAttributeMaxDynamicSharedMemorySize, REC_SMEM_BYTES);
    cudaFuncSetAttribute(gx_kernel,
                         cudaFuncAttributeMaxDynamicSharedMemorySize, GX_SMEM_BYTES);

    prep_kernel<<<4096, 256>>>(x, hidden, emb, Wf, Uf, Wb, Ub);
    dim3 ggx(48, NT, 2);
    gx_kernel<<<ggx, 256, GX_SMEM_BYTES>>>(x, bf_in, bb_in);
    recurrent_kernel<<<REC_BLOCKS, 256, REC_SMEM_BYTES>>>(bf_rec, bb_rec, Wp, bp, out);
}

// round 12
// speedup vs baseline: 1.1993x; 1.1993x over previous
#include <cuda_runtime.h>
#include <cuda_bf16.h>
#include <cstdint>
#include <math.h>

#define VOCAB 32000
#define EMB   256
#define UNITS 1024
#define NB    64
#define NT    256
#define G3    3072
#define REC_BLOCKS 128

typedef unsigned long long ull;

// ---------------- device scratch ---------------------------------------------------
__device__ float g_gx[(size_t)2 * NT * NB * G3];         // packed gate-major inputs
__device__ __nv_bfloat16 g_ubfT[2][2][G3][UNITS];        // [split][dir][p][k] U^T hi/lo
__device__ ull  g_wbfF[2 * 16 * 384 * 64];               // W frags [dir][ks][pt][lane][sp]
__device__ __nv_bfloat16 g_embbf[2][VOCAB][EMB];         // emb hi/lo
__device__ float g_h [2][2][NB][UNITS];                  // fp32 h, [dir][pp][b][u]
__device__ __nv_bfloat16 g_hbf[2][2][2][NB][UNITS];      // [split][dir][pp][b][u]
__device__ unsigned char g_mask[2][NT][NB];
__device__ unsigned g_bar_count;
__device__ unsigned g_bar_gen;
__device__ unsigned g_cnt2[2][32];                       // per-dir barrier (padded lines)
__device__ unsigned g_gen2[2][32];

// ---------------- helpers -----------------------------------------------------------
__device__ __forceinline__ uint32_t smem_u32(const void* p) {
    uint32_t a;
    asm("{ .reg .u64 t; cvta.to.shared.u64 t, %1; cvt.u32.u64 %0, t; }" : "=r"(a) : "l"(p));
    return a;
}
__device__ __forceinline__ unsigned short bfbits(__nv_bfloat16 v) {
    return *(unsigned short*)&v;
}

#define CP_ASYNC16(dst, src) \
    asm volatile("cp.async.cg.shared.global [%0], [%1], 16;" :: "r"(dst), "l"(src) : "memory")
#define CP_COMMIT() asm volatile("cp.async.commit_group;" ::: "memory")
#define CP_WAIT0()  asm volatile("cp.async.wait_group 0;" ::: "memory")
#define NAMED_BAR(id) asm volatile("bar.sync %0, 64;" :: "r"(id) : "memory")

#define LDMATRIX_X4(r0, r1, r2, r3, addr) \
    asm volatile("ldmatrix.sync.aligned.m8n8.x4.shared.b16 {%0,%1,%2,%3}, [%4];" \
                 : "=r"(r0), "=r"(r1), "=r"(r2), "=r"(r3) : "r"(addr))

#define MMA_BF16(c, a0, a1, a2, a3, b0, b1) \
    asm volatile("mma.sync.aligned.m16n8k16.row.col.f32.bf16.bf16.f32 " \
                 "{%0,%1,%2,%3}, {%4,%5,%6,%7}, {%8,%9}, {%0,%1,%2,%3};" \
                 : "+f"((c)[0]), "+f"((c)[1]), "+f"((c)[2]), "+f"((c)[3]) \
                 : "r"(a0), "r"(a1), "r"(a2), "r"(a3), "r"(b0), "r"(b1))

__device__ __forceinline__ void barrier_generic(unsigned* cnt, unsigned* gen,
                                                unsigned nblk, unsigned target) {
    __syncthreads();
    if (threadIdx.x == 0) {
        unsigned prev;
        asm volatile("atom.acq_rel.gpu.add.u32 %0, [%1], 1;"
                     : "=r"(prev) : "l"(cnt) : "memory");
        if (prev == target * nblk - 1u) {
            asm volatile("st.release.gpu.u32 [%0], %1;"
                         :: "l"(gen), "r"(target) : "memory");
        } else {
            unsigned g;
            do {
                asm volatile("ld.acquire.gpu.u32 %0, [%1];"
                             : "=r"(g) : "l"(gen) : "memory");
            } while (g < target);
        }
    }
    __syncthreads();
}

// ---------------- prep ---------------------------------------------------------------
__global__ void prep_kernel(const int* __restrict__ x, const float* __restrict__ hidden,
                            const float* __restrict__ emb,
                            const float* __restrict__ Wf, const float* __restrict__ Uf,
                            const float* __restrict__ Wb, const float* __restrict__ Ub) {
    const long long NUBF = 2LL * 2 * G3 * UNITS;          // U^T hi/lo
    const long long NWF  = 2LL * 16 * 384 * 64;           // W frags
    const long long NEMB = 2LL * VOCAB * EMB;             // emb hi/lo
    const long long NM   = 2LL * NT * NB;
    const long long NH   = 2LL * NB * UNITS;
    const long long NHBF = 2LL * 2 * NB * UNITS;
    const long long total = NUBF + NWF + NEMB + NM + NH + NHBF;
    const long long stride = (long long)gridDim.x * blockDim.x;
    for (long long i = (long long)blockIdx.x * blockDim.x + threadIdx.x; i < total; i += stride) {
        if (i < NUBF) {
            int split = (int)(i / (2LL * G3 * UNITS));
            long long r1 = i - (long long)split * 2 * G3 * UNITS;
            int dir = (int)(r1 / ((long long)G3 * UNITS));
            long long r2 = r1 - (long long)dir * G3 * UNITS;
            int p = (int)(r2 / UNITS);
            int k = (int)(r2 % UNITS);
            const float* U = dir ? Ub : Uf;
            float val = U[(long long)k * G3 + (p % 3) * UNITS + p / 3];
            __nv_bfloat16 hi = __float2bfloat16(val);
            if (split == 0) g_ubfT[0][dir][p][k] = hi;
            else            g_ubfT[1][dir][p][k] = __float2bfloat16(val - __bfloat162float(hi));
        } else if (i < NUBF + NWF) {
            long long j = i - NUBF;
            int dir = (int)(j / (16LL * 384 * 64));
            int r = (int)(j % (16LL * 384 * 64));
            int ks = r / (384 * 64); r %= 384 * 64;
            int pt = r / 64; r %= 64;
            int lane = r >> 1;
            int sp = r & 1;
            int gid = lane >> 2, tig = lane & 3;
            int p = pt * 8 + gid;
            const float* W = dir ? Wb : Wf;
            const long long poff = (long long)(p % 3) * UNITS + p / 3;
            int k0 = ks * 16 + 2 * tig;
            float v0 = W[(long long)(k0 + 0) * G3 + poff];
            float v1 = W[(long long)(k0 + 1) * G3 + poff];
            float v2 = W[(long long)(k0 + 8) * G3 + poff];
            float v3 = W[(long long)(k0 + 9) * G3 + poff];
            unsigned short b0, b1, b2, b3;
            if (sp == 0) {
                b0 = bfbits(__float2bfloat16(v0)); b1 = bfbits(__float2bfloat16(v1));
                b2 = bfbits(__float2bfloat16(v2)); b3 = bfbits(__float2bfloat16(v3));
            } else {
                __nv_bfloat16 h0 = __float2bfloat16(v0), h1 = __float2bfloat16(v1);
                __nv_bfloat16 h2 = __float2bfloat16(v2), h3 = __float2bfloat16(v3);
                b0 = bfbits(__float2bfloat16(v0 - __bfloat162float(h0)));
                b1 = bfbits(__float2bfloat16(v1 - __bfloat162float(h1)));
                b2 = bfbits(__float2bfloat16(v2 - __bfloat162float(h2)));
                b3 = bfbits(__float2bfloat16(v3 - __bfloat162float(h3)));
            }
            g_wbfF[j] = (ull)b0 | ((ull)b1 << 16) | ((ull)b2 << 32) | ((ull)b3 << 48);
        } else if (i < NUBF + NWF + NEMB) {
            long long j = i - NUBF - NWF;
            int sp = (int)(j / ((long long)VOCAB * EMB));
            long long rem = j - (long long)sp * VOCAB * EMB;
            int e = (int)(rem / EMB), c = (int)(rem % EMB);
            float val = emb[(long long)e * EMB + c];
            __nv_bfloat16 hi = __float2bfloat16(val);
            if (sp == 0) g_embbf[0][e][c] = hi;
            else         g_embbf[1][e][c] = __float2bfloat16(val - __bfloat162float(hi));
        } else if (i < NUBF + NWF + NEMB + NM) {
            long long j = i - NUBF - NWF - NEMB;
            int dir = (int)(j / (NT * NB));
            int rem = (int)(j % (NT * NB));
            int s = rem / NB, b = rem % NB;
            int t = dir ? (NT - 1 - s) : s;
            g_mask[dir][s][b] = (x[b * NT + t] != 0) ? 1 : 0;
        } else if (i < NUBF + NWF + NEMB + NM + NH) {
            long long j = i - NUBF - NWF - NEMB - NM;
            int dir = (int)(j / (NB * UNITS));
            int rem = (int)(j % (NB * UNITS));
            int b = rem / UNITS, u = rem % UNITS;
            g_h[dir][0][b][u] = hidden[b * UNITS + u];
        } else {
            long long j = i - NUBF - NWF - NEMB - NM - NH;
            int split = (int)(j / (2LL * NB * UNITS));
            long long r1 = j - (long long)split * 2 * NB * UNITS;
            int dir = (int)(r1 / (NB * UNITS));
            int rem = (int)(r1 % (NB * UNITS));
            int b = rem / UNITS, u = rem % UNITS;
            float val = hidden[b * UNITS + u];
            __nv_bfloat16 hi = __float2bfloat16(val);
            if (split == 0) g_hbf[0][dir][0][b][u] = hi;
            else            g_hbf[1][dir][0][b][u] = __float2bfloat16(val - __bfloat162float(hi));
        }
    }
    if (blockIdx.x == 0 && threadIdx.x == 0) {
        g_bar_count = 0u; g_bar_gen = 0u;
        g_cnt2[0][0] = 0u; g_cnt2[1][0] = 0u;
        g_gen2[0][0] = 0u; g_gen2[1][0] = 0u;
    }
}

// ---------------- gx via HMMA: C[64x64] = xe[64x256] @ W[64x256]^T, 3-term split ----
#define GX_SMEM_BYTES (65536 + 512)
__global__ __launch_bounds__(256) void gx_kernel(const int* __restrict__ x,
                                                 const float* __restrict__ bf_in,
                                                 const float* __restrict__ bb_in) {
    extern __shared__ char smx[];
    const uint32_t smb = smem_u32(smx);
    int* toks = (int*)(smx + 65536);

    const int ct  = blockIdx.x;
    const int t   = blockIdx.y;
    const int dir = blockIdx.z;
    const int tid = threadIdx.x;
    const int wid = tid >> 5;
    const int lane = tid & 31;
    const int mi = wid & 3;
    const int nj = wid >> 2;
    const int gid = lane >> 2;
    const int tig = lane & 3;

    if (tid < 64) {
        int tt = dir ? (NT - 1 - t) : t;
        toks[tid] = x[tid * NT + tt];
    }
    __syncthreads();

    // stage A (xe hi/lo), swizzled 16B granules in 512B rows
#pragma unroll
    for (int j = 0; j < 16; j++) {
        int f = tid + j * 256;
        int sp = f >> 11;
        int rem = f & 2047;
        int row = rem >> 5;
        int seg = rem & 31;
        const void* src = &g_embbf[sp][toks[row]][seg * 8];
        uint32_t dst = smb + (uint32_t)sp * 32768u + (uint32_t)(row * 512)
                     + (uint32_t)((seg ^ (row & 7)) << 4);
        CP_ASYNC16(dst, src);
    }
    CP_COMMIT();
    CP_WAIT0();
    __syncthreads();

    float c[4][4];
#pragma unroll
    for (int i = 0; i < 4; i++) { c[i][0] = 0.f; c[i][1] = 0.f; c[i][2] = 0.f; c[i][3] = 0.f; }

    const int arow = mi * 16 + (lane & 15);
    const int acb  = lane >> 4;
    const uint32_t abase = smb + (uint32_t)(arow * 512);
    const ull* wf = g_wbfF + (size_t)dir * 16 * 384 * 64;

#pragma unroll
    for (int ks = 0; ks < 16; ks++) {
        const int seg = ks * 2 + acb;
        const uint32_t sw = (uint32_t)((seg ^ (arow & 7)) << 4);
        uint32_t ah0, ah1, ah2, ah3, al0, al1, al2, al3;
        LDMATRIX_X4(ah0, ah1, ah2, ah3, abase + sw);
        LDMATRIX_X4(al0, al1, al2, al3, abase + 32768u + sw);
        ull vh[4], vl[4];
#pragma unroll
        for (int ntl = 0; ntl < 4; ntl++) {
            size_t base = ((size_t)ks * 384 + ct * 8 + nj * 4 + ntl) * 64 + lane * 2;
            ulonglong2 v = __ldg((const ulonglong2*)(wf + base));
            vh[ntl] = v.x;
            vl[ntl] = v.y;
        }
#pragma unroll
        for (int ntl = 0; ntl < 4; ntl++)
            MMA_BF16(c[ntl], ah0, ah1, ah2, ah3, (uint32_t)vh[ntl], (uint32_t)(vh[ntl] >> 32));
#pragma unroll
        for (int ntl = 0; ntl < 4; ntl++)
            MMA_BF16(c[ntl], al0, al1, al2, al3, (uint32_t)vh[ntl], (uint32_t)(vh[ntl] >> 32));
#pragma unroll
        for (int ntl = 0; ntl < 4; ntl++)
            MMA_BF16(c[ntl], ah0, ah1, ah2, ah3, (uint32_t)vl[ntl], (uint32_t)(vl[ntl] >> 32));
    }

    // redistribute C through smem
    __syncthreads();
    float* Cb = (float*)smx;              // [64][68]
    {
        const int r0 = mi * 16 + gid;
#pragma unroll
        for (int ntl = 0; ntl < 4; ntl++) {
            const int col = nj * 32 + ntl * 8 + 2 * tig;
            *(float2*)&Cb[r0 * 68 + col]       = make_float2(c[ntl][0], c[ntl][1]);
            *(float2*)&Cb[(r0 + 8) * 68 + col] = make_float2(c[ntl][2], c[ntl][3]);
        }
    }
    __syncthreads();

    // epilogue: + b_in, write packed gx
    {
        const int b   = tid & 63;
        const int grp = tid >> 6;
        const int pbase = ct * 64;
        const float* bsrc = dir ? bb_in : bf_in;
        float o[16];
#pragma unroll
        for (int q = 0; q < 16; q++) {
            int p = pbase + grp * 16 + q;
            o[q] = Cb[b * 68 + grp * 16 + q] + __ldg(bsrc + (p % 3) * UNITS + p / 3);
        }
        float* gxp = g_gx + ((size_t)(dir * NT + t) * NB + b) * G3 + pbase + grp * 16;
#pragma unroll
        for (int q = 0; q < 4; q++)
            *(float4*)(gxp + q * 4) = *(const float4*)&o[q * 4];
    }
}

// ---------------- persistent HMMA recurrent kernel -----------------------------------
// Per-pair cp.async staging with named barriers; per-dir step barrier (R10-proven).
#define ABUF_OFF    196608u
#define BIAS_OFF    229376u
#define REC_SMEM_BYTES 229568

__global__ __launch_bounds__(256, 1) void recurrent_kernel(const float* __restrict__ bf_rec,
                                                           const float* __restrict__ bb_rec,
                                                           const float* __restrict__ Wp,
                                                           const float* __restrict__ bp,
                                                           float* __restrict__ out) {
    extern __shared__ char smx[];
    const uint32_t smb = smem_u32(smx);

    const int blk   = blockIdx.x;
    const int dir   = blk >> 6;
    const int utile = blk & 63;
    const int pbase = utile * 48;
    const int ubase = utile * 16;
    const int tid  = threadIdx.x;
    const int wid  = tid >> 5;
    const int lane = tid & 31;
    const int mi = wid & 3;
    const int nj = wid >> 2;
    const int gid = lane >> 2;
    const int tig = lane & 3;

    if (tid < 48) {
        const float* brec = dir ? bb_rec : bf_rec;
        ((float*)(smx + BIAS_OFF))[tid] = brec[(tid % 3) * UNITS + ubase + tid / 3];
    }

    // fragment-ordered U in smem, hi/lo PAIRED in 16B: [pair = ksg*6 + ntile][lane]
    for (int e = wid; e < 384; e += 8) {
        int ks = e / 6;
        int nt = e % 6;
        int p  = pbase + nt * 8 + gid;
        const __nv_bfloat16* uh = &g_ubfT[0][dir][p][ks * 16 + 2 * tig];
        const __nv_bfloat16* ul = &g_ubfT[1][dir][p][ks * 16 + 2 * tig];
        ulonglong2 v;
        v.x = (ull)(*(const uint32_t*)uh) | ((ull)(*(const uint32_t*)(uh + 8)) << 32);
        v.y = (ull)(*(const uint32_t*)ul) | ((ull)(*(const uint32_t*)(ul + 8)) << 32);
        *(ulonglong2*)(smx + ((size_t)e * 32 + lane) * 16) = v;
    }
    __syncthreads();

    const int b_ep = tid & 63;
    const int usub = tid >> 6;
    const int bar_id = 1 + mi;           // pair barrier id (warps mi and mi+4)

    // per-warp staging constants: warp loads split nj, rows mi*16..+15, 4 granules/lane
    const int st_row = mi * 16 + (lane >> 1);          // 2 lanes per row
    const int st_sega = (lane & 1) * 4;                // segs 0-3 or 4-7 (+q)
    const uint32_t st_dst_base = smb + ABUF_OFF + (uint32_t)nj * 8192u
                               + (uint32_t)(st_row * 128);

    for (int s = 0; s < NT; s++) {
        const int pp  = s & 1;
        const int ppn = pp ^ 1;

        float gxv[12];
        {
            const float* gxr = g_gx + ((size_t)(dir * NT + s) * NB + b_ep) * G3 + pbase + usub * 12;
#pragma unroll
            for (int q = 0; q < 3; q++)
                *(float4*)&gxv[q * 4] = __ldcs((const float4*)(gxr + q * 4));
        }
        float hp[4];
        *(float4*)hp = __ldcg((const float4*)(&g_h[dir][pp][b_ep][ubase + usub * 4]));
        const int m = g_mask[dir][s][b_ep];

        const __nv_bfloat16* hsrc = &g_hbf[nj][dir][pp][st_row][0];

        // stage chunk 0 (this warp's split, this pair's rows)
        {
#pragma unroll
            for (int q = 0; q < 4; q++) {
                int seg = st_sega + q;
                CP_ASYNC16(st_dst_base + (uint32_t)((seg ^ (st_row & 7)) * 16),
                           hsrc + seg * 8);
            }
            CP_COMMIT();
        }

        float c[3][4];
#pragma unroll
        for (int i = 0; i < 3; i++) { c[i][0] = 0.f; c[i][1] = 0.f; c[i][2] = 0.f; c[i][3] = 0.f; }

        const int arow = mi * 16 + (lane & 15);
        const int acb  = lane >> 4;

        for (int ci = 0; ci < 16; ci++) {
            CP_WAIT0();
            NAMED_BAR(bar_id);           // pair: chunk ci fully staged, ci-1 fully consumed
            if (ci < 15) {
                const uint32_t slot_dst = st_dst_base + (uint32_t)((ci + 1) & 1) * 16384u;
                const __nv_bfloat16* src = hsrc + (ci + 1) * 64;
#pragma unroll
                for (int q = 0; q < 4; q++) {
                    int seg = st_sega + q;
                    CP_ASYNC16(slot_dst + (uint32_t)((seg ^ (st_row & 7)) * 16),
                               src + seg * 8);
                }
                CP_COMMIT();
            }
            const uint32_t abase = smb + ABUF_OFF + (uint32_t)(ci & 1) * 16384u
                                 + (uint32_t)(arow * 128);
#pragma unroll
            for (int ks = 0; ks < 4; ks++) {
                const int seg = ks * 2 + acb;
                const uint32_t sw = (uint32_t)((seg ^ (arow & 7)) * 16);
                uint32_t ah0, ah1, ah2, ah3, al0, al1, al2, al3;
                LDMATRIX_X4(ah0, ah1, ah2, ah3, abase + sw);
                LDMATRIX_X4(al0, al1, al2, al3, abase + 8192u + sw);
                const int ksg = ci * 4 + ks;
                ull vh[3], vl[3];
#pragma unroll
                for (int ntl = 0; ntl < 3; ntl++) {
                    ulonglong2 v = *(const ulonglong2*)
                        (smx + ((size_t)(ksg * 6 + nj * 3 + ntl) * 32 + lane) * 16);
                    vh[ntl] = v.x;
                    vl[ntl] = v.y;
                }
#pragma unroll
                for (int ntl = 0; ntl < 3; ntl++)
                    MMA_BF16(c[ntl], ah0, ah1, ah2, ah3, (uint32_t)vh[ntl], (uint32_t)(vh[ntl] >> 32));
#pragma unroll
                for (int ntl = 0; ntl < 3; ntl++)
                    MMA_BF16(c[ntl], al0, al1, al2, al3, (uint32_t)vh[ntl], (uint32_t)(vh[ntl] >> 32));
#pragma unroll
                for (int ntl = 0; ntl < 3; ntl++)
                    MMA_BF16(c[ntl], ah0, ah1, ah2, ah3, (uint32_t)vl[ntl], (uint32_t)(vl[ntl] >> 32));
            }
        }

        // redistribute C through smem (block-wide)
        __syncthreads();
        float* Cb = (float*)(smx + ABUF_OFF);
        {
            const int r0 = mi * 16 + gid;
#pragma unroll
            for (int ntl = 0; ntl < 3; ntl++) {
                const int col = nj * 24 + ntl * 8 + 2 * tig;
                *(float2*)&Cb[r0 * 52 + col]       = make_float2(c[ntl][0], c[ntl][1]);
                *(float2*)&Cb[(r0 + 8) * 52 + col] = make_float2(c[ntl][2], c[ntl][3]);
            }
        }
        __syncthreads();

        // GRU epilogue
        {
            float acc[12];
#pragma unroll
            for (int q = 0; q < 3; q++)
                *(float4*)&acc[q * 4] = *(const float4*)&Cb[b_ep * 52 + usub * 12 + q * 4];
            const float* sb = (const float*)(smx + BIAS_OFF) + usub * 12;
            const int tt = dir ? (NT - 1 - s) : s;

            float hn[4];
            __nv_bfloat16 hi4[4], lo4[4];
#pragma unroll
            for (int ul = 0; ul < 4; ul++) {
                float z = 1.f / (1.f + expf(-(gxv[ul * 3 + 0] + acc[ul * 3 + 0] + sb[ul * 3 + 0])));
                float r = 1.f / (1.f + expf(-(gxv[ul * 3 + 1] + acc[ul * 3 + 1] + sb[ul * 3 + 1])));
                float hh = tanhf(gxv[ul * 3 + 2] + r * (acc[ul * 3 + 2] + sb[ul * 3 + 2]));
                float v = z * hp[ul] + (1.f - z) * hh;
                if (!m) v = hp[ul];
                hn[ul] = v;
                __nv_bfloat16 hi = __float2bfloat16(v);
                hi4[ul] = hi;
                lo4[ul] = __float2bfloat16(v - __bfloat162float(hi));
            }
            const int uo = ubase + usub * 4;
            *(float4*)(out + ((size_t)b_ep * NT + tt) * (2 * UNITS) + dir * UNITS + uo)
                = *(const float4*)hn;
            *(float4*)(&g_h[dir][ppn][b_ep][uo]) = *(const float4*)hn;
            *(uint2*)(&g_hbf[0][dir][ppn][b_ep][uo]) = *(const uint2*)hi4;
            *(uint2*)(&g_hbf[1][dir][ppn][b_ep][uo]) = *(const uint2*)lo4;
        }

        barrier_generic(&g_cnt2[dir][0], &g_gen2[dir][0], 64u, (unsigned)(s + 1));
    }

    // full barrier before cross-dir final state
    barrier_generic(&g_bar_count, &g_bar_gen, 128u, 1u);

    // fused final state: tanh(concat(hf,hb) @ Wp + bp), final h in pingpong buffer 0
    {
        float* sst = (float*)smx;
        const int tx8 = tid & 7;
        const int tyS = tid >> 3;
        const int b0 = tyS * 2;
        const int ocol = blk * 8 + tx8;
        const float* wp = Wp + ocol;
        float acc0 = 0.f, acc1 = 0.f;
        for (int k0 = 0; k0 < 2 * UNITS; k0 += 128) {
            __syncthreads();
#pragma unroll
            for (int j = 0; j < 8; j++) {
                int f = tid + j * 256;
                int b = f >> 5;
                int k4 = (f & 31) << 2;
                int gk = k0 + k4;
                float4 v = __ldcg((const float4*)(&g_h[gk >> 10][0][b][gk & 1023]));
                *(float4*)&sst[b * 132 + k4] = v;
            }
            __syncthreads();
#pragma unroll 8
            for (int kk = 0; kk < 128; kk++) {
                float w = __ldg(wp + (size_t)(k0 + kk) * UNITS);
                acc0 = fmaf(sst[b0 * 132 + kk], w, acc0);
                acc1 = fmaf(sst[(b0 + 1) * 132 + kk], w, acc1);
            }
        }
        float bpv = bp[ocol];
        const size_t so = (size_t)NB * NT * (2 * UNITS);
        out[so + (size_t)b0 * UNITS + ocol]       = tanhf(acc0 + bpv);
        out[so + (size_t)(b0 + 1) * UNITS + ocol] = tanhf(acc1 + bpv);
    }
}

// ---------------- launch --------------------------------------------------------------
extern "C" void kernel_launch(void* const* d_in, const int* in_sizes, int n_in,
                              void* d_out, int out_size) {
    (void)in_sizes; (void)n_in; (void)out_size;
    const int*   x      = (const int*)  d_in[0];
    const float* hidden = (const float*)d_in[1];
    const float* emb    = (const float*)d_in[2];
    const float* Wf     = (const float*)d_in[3];
    const float* Uf     = (const float*)d_in[4];
    const float* bf_in  = (const float*)d_in[5];
    const float* bf_rec = (const float*)d_in[6];
    const float* Wb     = (const float*)d_in[7];
    const float* Ub     = (const float*)d_in[8];
    const float* bb_in  = (const float*)d_in[9];
    const float* bb_rec = (const float*)d_in[10];
    const float* Wp     = (const float*)d_in[11];
    const float* bp     = (const float*)d_in[12];
    float* out = (float*)d_out;

    cudaFuncSetAttribute(recurrent_kernel,
                         cudaFuncAttributeMaxDynamicSharedMemorySize, REC_SMEM_BYTES);
    cudaFuncSetAttribute(gx_kernel,
                         cudaFuncAttributeMaxDynamicSharedMemorySize, GX_SMEM_BYTES);

    prep_kernel<<<4096, 256>>>(x, hidden, emb, Wf, Uf, Wb, Ub);
    dim3 ggx(48, NT, 2);
    gx_kernel<<<ggx, 256, GX_SMEM_BYTES>>>(x, bf_in, bb_in);
    recurrent_kernel<<<REC_BLOCKS, 256, REC_SMEM_BYTES>>>(bf_rec, bb_rec, Wp, bp, out);
}

// round 13
// speedup vs baseline: 1.2662x; 1.0557x over previous
#include <cuda_runtime.h>
#include <cuda_fp16.h>
#include <cstdint>
#include <math.h>

#define VOCAB 32000
#define EMB   256
#define UNITS 1024
#define NB    64
#define NT    256
#define G3    3072
#define REC_BLOCKS 128

typedef unsigned long long ull;

// ---------------- device scratch ---------------------------------------------------
__device__ float g_gx[(size_t)2 * NT * NB * G3];         // packed gate-major inputs
__device__ __half g_uh[2][G3][UNITS];                    // [dir][p][k] U^T fp16 (hi only)
__device__ ull  g_wbfF[2 * 16 * 384 * 32];               // W frags fp16-hi [dir][ks][pt][lane]
__device__ __half g_embh[2][VOCAB][EMB];                 // emb fp16 hi/lo
__device__ float g_h [2][2][NB][UNITS];                  // fp32 h, [dir][pp][b][u]
__device__ __half g_hhf[2][2][2][NB][UNITS];             // [split][dir][pp][b][u] fp16
__device__ unsigned char g_mask[2][NT][NB];
__device__ unsigned g_bar_count;
__device__ unsigned g_bar_gen;
__device__ unsigned g_cnt2[2][32];                       // per-dir barrier (padded lines)
__device__ unsigned g_gen2[2][32];

// ---------------- helpers -----------------------------------------------------------
__device__ __forceinline__ uint32_t smem_u32(const void* p) {
    uint32_t a;
    asm("{ .reg .u64 t; cvta.to.shared.u64 t, %1; cvt.u32.u64 %0, t; }" : "=r"(a) : "l"(p));
    return a;
}
__device__ __forceinline__ unsigned short hfbits(__half v) {
    return *(unsigned short*)&v;
}

#define CP_ASYNC16(dst, src) \
    asm volatile("cp.async.cg.shared.global [%0], [%1], 16;" :: "r"(dst), "l"(src) : "memory")
#define CP_COMMIT() asm volatile("cp.async.commit_group;" ::: "memory")
#define CP_WAIT0()  asm volatile("cp.async.wait_group 0;" ::: "memory")
#define NAMED_BAR(id) asm volatile("bar.sync %0, 64;" :: "r"(id) : "memory")

#define LDMATRIX_X4(r0, r1, r2, r3, addr) \
    asm volatile("ldmatrix.sync.aligned.m8n8.x4.shared.b16 {%0,%1,%2,%3}, [%4];" \
                 : "=r"(r0), "=r"(r1), "=r"(r2), "=r"(r3) : "r"(addr))

#define MMA_F16(c, a0, a1, a2, a3, b0, b1) \
    asm volatile("mma.sync.aligned.m16n8k16.row.col.f32.f16.f16.f32 " \
                 "{%0,%1,%2,%3}, {%4,%5,%6,%7}, {%8,%9}, {%0,%1,%2,%3};" \
                 : "+f"((c)[0]), "+f"((c)[1]), "+f"((c)[2]), "+f"((c)[3]) \
                 : "r"(a0), "r"(a1), "r"(a2), "r"(a3), "r"(b0), "r"(b1))

__device__ __forceinline__ void barrier_generic(unsigned* cnt, unsigned* gen,
                                                unsigned nblk, unsigned target) {
    __syncthreads();
    if (threadIdx.x == 0) {
        unsigned prev;
        asm volatile("atom.acq_rel.gpu.add.u32 %0, [%1], 1;"
                     : "=r"(prev) : "l"(cnt) : "memory");
        if (prev == target * nblk - 1u) {
            asm volatile("st.release.gpu.u32 [%0], %1;"
                         :: "l"(gen), "r"(target) : "memory");
        } else {
            unsigned g;
            do {
                asm volatile("ld.acquire.gpu.u32 %0, [%1];"
                             : "=r"(g) : "l"(gen) : "memory");
            } while (g < target);
        }
    }
    __syncthreads();
}

// ---------------- prep ---------------------------------------------------------------
__global__ void prep_kernel(const int* __restrict__ x, const float* __restrict__ hidden,
                            const float* __restrict__ emb,
                            const float* __restrict__ Wf, const float* __restrict__ Uf,
                            const float* __restrict__ Wb, const float* __restrict__ Ub) {
    const long long NUH  = 2LL * G3 * UNITS;              // U fp16 hi
    const long long NWF  = 2LL * 16 * 384 * 32;           // W frags (hi only)
    const long long NEMB = 2LL * VOCAB * EMB;             // emb hi/lo
    const long long NM   = 2LL * NT * NB;
    const long long NH   = 2LL * NB * UNITS;
    const long long NHHF = 2LL * 2 * NB * UNITS;
    const long long total = NUH + NWF + NEMB + NM + NH + NHHF;
    const long long stride = (long long)gridDim.x * blockDim.x;
    for (long long i = (long long)blockIdx.x * blockDim.x + threadIdx.x; i < total; i += stride) {
        if (i < NUH) {
            int dir = (int)(i / ((long long)G3 * UNITS));
            long long r2 = i - (long long)dir * G3 * UNITS;
            int p = (int)(r2 / UNITS);
            int k = (int)(r2 % UNITS);
            const float* U = dir ? Ub : Uf;
            g_uh[dir][p][k] = __float2half(U[(long long)k * G3 + (p % 3) * UNITS + p / 3]);
        } else if (i < NUH + NWF) {
            long long j = i - NUH;
            int dir = (int)(j / (16LL * 384 * 32));
            int r = (int)(j % (16LL * 384 * 32));
            int ks = r / (384 * 32); r %= 384 * 32;
            int pt = r / 32;
            int lane = r % 32;
            int gid = lane >> 2, tig = lane & 3;
            int p = pt * 8 + gid;
            const float* W = dir ? Wb : Wf;
            const long long poff = (long long)(p % 3) * UNITS + p / 3;
            int k0 = ks * 16 + 2 * tig;
            unsigned short b0 = hfbits(__float2half(W[(long long)(k0 + 0) * G3 + poff]));
            unsigned short b1 = hfbits(__float2half(W[(long long)(k0 + 1) * G3 + poff]));
            unsigned short b2 = hfbits(__float2half(W[(long long)(k0 + 8) * G3 + poff]));
            unsigned short b3 = hfbits(__float2half(W[(long long)(k0 + 9) * G3 + poff]));
            g_wbfF[j] = (ull)b0 | ((ull)b1 << 16) | ((ull)b2 << 32) | ((ull)b3 << 48);
        } else if (i < NUH + NWF + NEMB) {
            long long j = i - NUH - NWF;
            int sp = (int)(j / ((long long)VOCAB * EMB));
            long long rem = j - (long long)sp * VOCAB * EMB;
            int e = (int)(rem / EMB), c = (int)(rem % EMB);
            float val = emb[(long long)e * EMB + c];
            __half hi = __float2half(val);
            if (sp == 0) g_embh[0][e][c] = hi;
            else         g_embh[1][e][c] = __float2half(val - __half2float(hi));
        } else if (i < NUH + NWF + NEMB + NM) {
            long long j = i - NUH - NWF - NEMB;
            int dir = (int)(j / (NT * NB));
            int rem = (int)(j % (NT * NB));
            int s = rem / NB, b = rem % NB;
            int t = dir ? (NT - 1 - s) : s;
            g_mask[dir][s][b] = (x[b * NT + t] != 0) ? 1 : 0;
        } else if (i < NUH + NWF + NEMB + NM + NH) {
            long long j = i - NUH - NWF - NEMB - NM;
            int dir = (int)(j / (NB * UNITS));
            int rem = (int)(j % (NB * UNITS));
            int b = rem / UNITS, u = rem % UNITS;
            g_h[dir][0][b][u] = hidden[b * UNITS + u];
        } else {
            long long j = i - NUH - NWF - NEMB - NM - NH;
            int split = (int)(j / (2LL * NB * UNITS));
            long long r1 = j - (long long)split * 2 * NB * UNITS;
            int dir = (int)(r1 / (NB * UNITS));
            int rem = (int)(r1 % (NB * UNITS));
            int b = rem / UNITS, u = rem % UNITS;
            float val = hidden[b * UNITS + u];
            __half hi = __float2half(val);
            if (split == 0) g_hhf[0][dir][0][b][u] = hi;
            else            g_hhf[1][dir][0][b][u] = __float2half(val - __half2float(hi));
        }
    }
    if (blockIdx.x == 0 && threadIdx.x == 0) {
        g_bar_count = 0u; g_bar_gen = 0u;
        g_cnt2[0][0] = 0u; g_cnt2[1][0] = 0u;
        g_gen2[0][0] = 0u; g_gen2[1][0] = 0u;
    }
}

// ---------------- gx via HMMA fp16 2-term: C = xe @ W^T --------------------------------
#define GX_SMEM_BYTES (65536 + 512)
__global__ __launch_bounds__(256) void gx_kernel(const int* __restrict__ x,
                                                 const float* __restrict__ bf_in,
                                                 const float* __restrict__ bb_in) {
    extern __shared__ char smx[];
    const uint32_t smb = smem_u32(smx);
    int* toks = (int*)(smx + 65536);

    const int ct  = blockIdx.x;
    const int t   = blockIdx.y;
    const int dir = blockIdx.z;
    const int tid = threadIdx.x;
    const int wid = tid >> 5;
    const int lane = tid & 31;
    const int mi = wid & 3;
    const int nj = wid >> 2;
    const int gid = lane >> 2;
    const int tig = lane & 3;

    if (tid < 64) {
        int tt = dir ? (NT - 1 - t) : t;
        toks[tid] = x[tid * NT + tt];
    }
    __syncthreads();

    // stage A (xe hi/lo fp16), swizzled 16B granules in 512B rows
#pragma unroll
    for (int j = 0; j < 16; j++) {
        int f = tid + j * 256;
        int sp = f >> 11;
        int rem = f & 2047;
        int row = rem >> 5;
        int seg = rem & 31;
        const void* src = &g_embh[sp][toks[row]][seg * 8];
        uint32_t dst = smb + (uint32_t)sp * 32768u + (uint32_t)(row * 512)
                     + (uint32_t)((seg ^ (row & 7)) << 4);
        CP_ASYNC16(dst, src);
    }
    CP_COMMIT();
    CP_WAIT0();
    __syncthreads();

    float c[4][4];
#pragma unroll
    for (int i = 0; i < 4; i++) { c[i][0] = 0.f; c[i][1] = 0.f; c[i][2] = 0.f; c[i][3] = 0.f; }

    const int arow = mi * 16 + (lane & 15);
    const int acb  = lane >> 4;
    const uint32_t abase = smb + (uint32_t)(arow * 512);
    const ull* wf = g_wbfF + (size_t)dir * 16 * 384 * 32;

#pragma unroll
    for (int ks = 0; ks < 16; ks++) {
        const int seg = ks * 2 + acb;
        const uint32_t sw = (uint32_t)((seg ^ (arow & 7)) << 4);
        uint32_t ah0, ah1, ah2, ah3, al0, al1, al2, al3;
        LDMATRIX_X4(ah0, ah1, ah2, ah3, abase + sw);
        LDMATRIX_X4(al0, al1, al2, al3, abase + 32768u + sw);
        ull vh[4];
#pragma unroll
        for (int ntl = 0; ntl < 4; ntl++)
            vh[ntl] = __ldg(wf + ((size_t)ks * 384 + ct * 8 + nj * 4 + ntl) * 32 + lane);
#pragma unroll
        for (int ntl = 0; ntl < 4; ntl++)
            MMA_F16(c[ntl], ah0, ah1, ah2, ah3, (uint32_t)vh[ntl], (uint32_t)(vh[ntl] >> 32));
#pragma unroll
        for (int ntl = 0; ntl < 4; ntl++)
            MMA_F16(c[ntl], al0, al1, al2, al3, (uint32_t)vh[ntl], (uint32_t)(vh[ntl] >> 32));
    }

    // redistribute C through smem
    __syncthreads();
    float* Cb = (float*)smx;              // [64][68]
    {
        const int r0 = mi * 16 + gid;
#pragma unroll
        for (int ntl = 0; ntl < 4; ntl++) {
            const int col = nj * 32 + ntl * 8 + 2 * tig;
            *(float2*)&Cb[r0 * 68 + col]       = make_float2(c[ntl][0], c[ntl][1]);
            *(float2*)&Cb[(r0 + 8) * 68 + col] = make_float2(c[ntl][2], c[ntl][3]);
        }
    }
    __syncthreads();

    // epilogue: + b_in, write packed gx
    {
        const int b   = tid & 63;
        const int grp = tid >> 6;
        const int pbase = ct * 64;
        const float* bsrc = dir ? bb_in : bf_in;
        float o[16];
#pragma unroll
        for (int q = 0; q < 16; q++) {
            int p = pbase + grp * 16 + q;
            o[q] = Cb[b * 68 + grp * 16 + q] + __ldg(bsrc + (p % 3) * UNITS + p / 3);
        }
        float* gxp = g_gx + ((size_t)(dir * NT + t) * NB + b) * G3 + pbase + grp * 16;
#pragma unroll
        for (int q = 0; q < 4; q++)
            *(float4*)(gxp + q * 4) = *(const float4*)&o[q * 4];
    }
}

// ---------------- persistent HMMA recurrent kernel (fp16 2-term) ----------------------
// U frags hi-only: 384 entries x 32 lanes x 8B = 98304 B
#define ABUF_OFF    98304u
#define BIAS_OFF    131072u
#define REC_SMEM_BYTES 131328

__global__ __launch_bounds__(256, 1) void recurrent_kernel(const float* __restrict__ bf_rec,
                                                           const float* __restrict__ bb_rec,
                                                           const float* __restrict__ Wp,
                                                           const float* __restrict__ bp,
                                                           float* __restrict__ out) {
    extern __shared__ char smx[];
    const uint32_t smb = smem_u32(smx);

    const int blk   = blockIdx.x;
    const int dir   = blk >> 6;
    const int utile = blk & 63;
    const int pbase = utile * 48;
    const int ubase = utile * 16;
    const int tid  = threadIdx.x;
    const int wid  = tid >> 5;
    const int lane = tid & 31;
    const int mi = wid & 3;
    const int nj = wid >> 2;
    const int gid = lane >> 2;
    const int tig = lane & 3;

    if (tid < 48) {
        const float* brec = dir ? bb_rec : bf_rec;
        ((float*)(smx + BIAS_OFF))[tid] = brec[(tid % 3) * UNITS + ubase + tid / 3];
    }

    // fragment-ordered U (hi only) in smem: [ksg*6 + ntile][lane] x 8B
    for (int e = wid; e < 384; e += 8) {
        int ks = e / 6;
        int nt = e % 6;
        int p  = pbase + nt * 8 + gid;
        const __half* uh = &g_uh[dir][p][ks * 16 + 2 * tig];
        ull v = (ull)(*(const uint32_t*)uh) | ((ull)(*(const uint32_t*)(uh + 8)) << 32);
        *(ull*)(smx + ((size_t)e * 32 + lane) * 8) = v;
    }
    __syncthreads();

    const int b_ep = tid & 63;
    const int usub = tid >> 6;
    const int bar_id = 1 + mi;           // pair barrier id (warps mi and mi+4)

    // per-warp staging: warp loads split nj, rows mi*16..+15, 4 granules/lane
    const int st_row = mi * 16 + (lane >> 1);
    const int st_sega = (lane & 1) * 4;
    const uint32_t st_dst_base = smb + ABUF_OFF + (uint32_t)nj * 8192u
                               + (uint32_t)(st_row * 128);

    for (int s = 0; s < NT; s++) {
        const int pp  = s & 1;
        const int ppn = pp ^ 1;

        float gxv[12];
        {
            const float* gxr = g_gx + ((size_t)(dir * NT + s) * NB + b_ep) * G3 + pbase + usub * 12;
#pragma unroll
            for (int q = 0; q < 3; q++)
                *(float4*)&gxv[q * 4] = __ldcs((const float4*)(gxr + q * 4));
        }
        float hp[4];
        *(float4*)hp = __ldcg((const float4*)(&g_h[dir][pp][b_ep][ubase + usub * 4]));
        const int m = g_mask[dir][s][b_ep];

        const __half* hsrc = &g_hhf[nj][dir][pp][st_row][0];

        // stage chunk 0
        {
#pragma unroll
            for (int q = 0; q < 4; q++) {
                int seg = st_sega + q;
                CP_ASYNC16(st_dst_base + (uint32_t)((seg ^ (st_row & 7)) * 16),
                           hsrc + seg * 8);
            }
            CP_COMMIT();
        }

        float c[3][4];
#pragma unroll
        for (int i = 0; i < 3; i++) { c[i][0] = 0.f; c[i][1] = 0.f; c[i][2] = 0.f; c[i][3] = 0.f; }

        const int arow = mi * 16 + (lane & 15);
        const int acb  = lane >> 4;

        for (int ci = 0; ci < 16; ci++) {
            CP_WAIT0();
            NAMED_BAR(bar_id);           // pair: chunk ci staged, ci-1 consumed
            if (ci < 15) {
                const uint32_t slot_dst = st_dst_base + (uint32_t)((ci + 1) & 1) * 16384u;
                const __half* src = hsrc + (ci + 1) * 64;
#pragma unroll
                for (int q = 0; q < 4; q++) {
                    int seg = st_sega + q;
                    CP_ASYNC16(slot_dst + (uint32_t)((seg ^ (st_row & 7)) * 16),
                               src + seg * 8);
                }
                CP_COMMIT();
            }
            const uint32_t abase = smb + ABUF_OFF + (uint32_t)(ci & 1) * 16384u
                                 + (uint32_t)(arow * 128);
#pragma unroll
            for (int ks = 0; ks < 4; ks++) {
                const int seg = ks * 2 + acb;
                const uint32_t sw = (uint32_t)((seg ^ (arow & 7)) * 16);
                uint32_t ah0, ah1, ah2, ah3, al0, al1, al2, al3;
                LDMATRIX_X4(ah0, ah1, ah2, ah3, abase + sw);
                LDMATRIX_X4(al0, al1, al2, al3, abase + 8192u + sw);
                const int ksg = ci * 4 + ks;
                ull vh[3];
#pragma unroll
                for (int ntl = 0; ntl < 3; ntl++)
                    vh[ntl] = *(const ull*)
                        (smx + ((size_t)(ksg * 6 + nj * 3 + ntl) * 32 + lane) * 8);
#pragma unroll
                for (int ntl = 0; ntl < 3; ntl++)
                    MMA_F16(c[ntl], ah0, ah1, ah2, ah3, (uint32_t)vh[ntl], (uint32_t)(vh[ntl] >> 32));
#pragma unroll
                for (int ntl = 0; ntl < 3; ntl++)
                    MMA_F16(c[ntl], al0, al1, al2, al3, (uint32_t)vh[ntl], (uint32_t)(vh[ntl] >> 32));
            }
        }

        // redistribute C through smem (block-wide)
        __syncthreads();
        float* Cb = (float*)(smx + ABUF_OFF);
        {
            const int r0 = mi * 16 + gid;
#pragma unroll
            for (int ntl = 0; ntl < 3; ntl++) {
                const int col = nj * 24 + ntl * 8 + 2 * tig;
                *(float2*)&Cb[r0 * 52 + col]       = make_float2(c[ntl][0], c[ntl][1]);
                *(float2*)&Cb[(r0 + 8) * 52 + col] = make_float2(c[ntl][2], c[ntl][3]);
            }
        }
        __syncthreads();

        // GRU epilogue
        {
            float acc[12];
#pragma unroll
            for (int q = 0; q < 3; q++)
                *(float4*)&acc[q * 4] = *(const float4*)&Cb[b_ep * 52 + usub * 12 + q * 4];
            const float* sb = (const float*)(smx + BIAS_OFF) + usub * 12;
            const int tt = dir ? (NT - 1 - s) : s;

            float hn[4];
            __half hi4[4], lo4[4];
#pragma unroll
            for (int ul = 0; ul < 4; ul++) {
                float z = 1.f / (1.f + expf(-(gxv[ul * 3 + 0] + acc[ul * 3 + 0] + sb[ul * 3 + 0])));
                float r = 1.f / (1.f + expf(-(gxv[ul * 3 + 1] + acc[ul * 3 + 1] + sb[ul * 3 + 1])));
                float hh = tanhf(gxv[ul * 3 + 2] + r * (acc[ul * 3 + 2] + sb[ul * 3 + 2]));
                float v = z * hp[ul] + (1.f - z) * hh;
                if (!m) v = hp[ul];
                hn[ul] = v;
                __half hi = __float2half(v);
                hi4[ul] = hi;
                lo4[ul] = __float2half(v - __half2float(hi));
            }
            const int uo = ubase + usub * 4;
            *(float4*)(out + ((size_t)b_ep * NT + tt) * (2 * UNITS) + dir * UNITS + uo)
                = *(const float4*)hn;
            *(float4*)(&g_h[dir][ppn][b_ep][uo]) = *(const float4*)hn;
            *(uint2*)(&g_hhf[0][dir][ppn][b_ep][uo]) = *(const uint2*)hi4;
            *(uint2*)(&g_hhf[1][dir][ppn][b_ep][uo]) = *(const uint2*)lo4;
        }

        barrier_generic(&g_cnt2[dir][0], &g_gen2[dir][0], 64u, (unsigned)(s + 1));
    }

    // full barrier before cross-dir final state
    barrier_generic(&g_bar_count, &g_bar_gen, 128u, 1u);

    // fused final state: tanh(concat(hf,hb) @ Wp + bp), final h in pingpong buffer 0
    {
        float* sst = (float*)smx;
        const int tx8 = tid & 7;
        const int tyS = tid >> 3;
        const int b0 = tyS * 2;
        const int ocol = blk * 8 + tx8;
        const float* wp = Wp + ocol;
        float acc0 = 0.f, acc1 = 0.f;
        for (int k0 = 0; k0 < 2 * UNITS; k0 += 128) {
            __syncthreads();
#pragma unroll
            for (int j = 0; j < 8; j++) {
                int f = tid + j * 256;
                int b = f >> 5;
                int k4 = (f & 31) << 2;
                int gk = k0 + k4;
                float4 v = __ldcg((const float4*)(&g_h[gk >> 10][0][b][gk & 1023]));
                *(float4*)&sst[b * 132 + k4] = v;
            }
            __syncthreads();
#pragma unroll 8
            for (int kk = 0; kk < 128; kk++) {
                float w = __ldg(wp + (size_t)(k0 + kk) * UNITS);
                acc0 = fmaf(sst[b0 * 132 + kk], w, acc0);
                acc1 = fmaf(sst[(b0 + 1) * 132 + kk], w, acc1);
            }
        }
        float bpv = bp[ocol];
        const size_t so = (size_t)NB * NT * (2 * UNITS);
        out[so + (size_t)b0 * UNITS + ocol]       = tanhf(acc0 + bpv);
        out[so + (size_t)(b0 + 1) * UNITS + ocol] = tanhf(acc1 + bpv);
    }
}

// ---------------- launch --------------------------------------------------------------
extern "C" void kernel_launch(void* const* d_in, const int* in_sizes, int n_in,
                              void* d_out, int out_size) {
    (void)in_sizes; (void)n_in; (void)out_size;
    const int*   x      = (const int*)  d_in[0];
    const float* hidden = (const float*)d_in[1];
    const float* emb    = (const float*)d_in[2];
    const float* Wf     = (const float*)d_in[3];
    const float* Uf     = (const float*)d_in[4];
    const float* bf_in  = (const float*)d_in[5];
    const float* bf_rec = (const float*)d_in[6];
    const float* Wb     = (const float*)d_in[7];
    const float* Ub     = (const float*)d_in[8];
    const float* bb_in  = (const float*)d_in[9];
    const float* bb_rec = (const float*)d_in[10];
    const float* Wp     = (const float*)d_in[11];
    const float* bp     = (const float*)d_in[12];
    float* out = (float*)d_out;

    cudaFuncSetAttribute(recurrent_kernel,
                         cudaFuncAttributeMaxDynamicSharedMemorySize, REC_SMEM_BYTES);
    cudaFuncSetAttribute(gx_kernel,
                         cudaFuncAttributeMaxDynamicSharedMemorySize, GX_SMEM_BYTES);

    prep_kernel<<<4096, 256>>>(x, hidden, emb, Wf, Uf, Wb, Ub);
    dim3 ggx(48, NT, 2);
    gx_kernel<<<ggx, 256, GX_SMEM_BYTES>>>(x, bf_in, bb_in);
    recurrent_kernel<<<REC_BLOCKS, 256, REC_SMEM_BYTES>>>(bf_rec, bb_rec, Wp, bp, out);
}

// round 14
// speedup vs baseline: 1.3298x; 1.0503x over previous
#include <cuda_runtime.h>
#include <cuda_fp16.h>
#include <cstdint>
#include <math.h>

#define VOCAB 32000
#define EMB   256
#define UNITS 1024
#define NB    64
#define NT    256
#define G3    3072
#define REC_BLOCKS 128

typedef unsigned long long ull;

// ---------------- device scratch ---------------------------------------------------
__device__ float g_gx[(size_t)2 * NT * NB * G3];         // packed gate-major inputs
__device__ __half g_uh[2][G3][UNITS];                    // [dir][p][k] U^T fp16 (hi only)
__device__ ull  g_wbfF[2 * 16 * 384 * 32];               // W frags fp16-hi [dir][ks][pt][lane]
__device__ __half g_embh[2][VOCAB][EMB];                 // emb fp16 hi/lo
__device__ float g_h [2][2][NB][UNITS];                  // fp32 h, [dir][pp][b][u]
__device__ __half g_hhf[2][2][2][NB][UNITS];             // [split][dir][pp][b][u] fp16
__device__ unsigned char g_mask[2][NT][NB];
__device__ unsigned g_bar_count;
__device__ unsigned g_bar_gen;
__device__ unsigned g_cnt2[2][32];                       // per-dir barrier (padded lines)
__device__ unsigned g_gen2[2][32];

// ---------------- helpers -----------------------------------------------------------
__device__ __forceinline__ uint32_t smem_u32(const void* p) {
    uint32_t a;
    asm("{ .reg .u64 t; cvta.to.shared.u64 t, %1; cvt.u32.u64 %0, t; }" : "=r"(a) : "l"(p));
    return a;
}
__device__ __forceinline__ unsigned short hfbits(__half v) {
    return *(unsigned short*)&v;
}

#define CP_ASYNC16(dst, src) \
    asm volatile("cp.async.cg.shared.global [%0], [%1], 16;" :: "r"(dst), "l"(src) : "memory")
#define CP_COMMIT() asm volatile("cp.async.commit_group;" ::: "memory")
#define CP_WAIT0()  asm volatile("cp.async.wait_group 0;" ::: "memory")
#define CP_WAIT1()  asm volatile("cp.async.wait_group 1;" ::: "memory")
#define NAMED_BAR(id) asm volatile("bar.sync %0, 64;" :: "r"(id) : "memory")

#define LDMATRIX_X4(r0, r1, r2, r3, addr) \
    asm volatile("ldmatrix.sync.aligned.m8n8.x4.shared.b16 {%0,%1,%2,%3}, [%4];" \
                 : "=r"(r0), "=r"(r1), "=r"(r2), "=r"(r3) : "r"(addr))

#define MMA_F16(c, a0, a1, a2, a3, b0, b1) \
    asm volatile("mma.sync.aligned.m16n8k16.row.col.f32.f16.f16.f32 " \
                 "{%0,%1,%2,%3}, {%4,%5,%6,%7}, {%8,%9}, {%0,%1,%2,%3};" \
                 : "+f"((c)[0]), "+f"((c)[1]), "+f"((c)[2]), "+f"((c)[3]) \
                 : "r"(a0), "r"(a1), "r"(a2), "r"(a3), "r"(b0), "r"(b1))

__device__ __forceinline__ void barrier_generic(unsigned* cnt, unsigned* gen,
                                                unsigned nblk, unsigned target) {
    __syncthreads();
    if (threadIdx.x == 0) {
        unsigned prev;
        asm volatile("atom.acq_rel.gpu.add.u32 %0, [%1], 1;"
                     : "=r"(prev) : "l"(cnt) : "memory");
        if (prev == target * nblk - 1u) {
            asm volatile("st.release.gpu.u32 [%0], %1;"
                         :: "l"(gen), "r"(target) : "memory");
        } else {
            unsigned g;
            do {
                asm volatile("ld.acquire.gpu.u32 %0, [%1];"
                             : "=r"(g) : "l"(gen) : "memory");
            } while (g < target);
        }
    }
    __syncthreads();
}

// ---------------- prep ---------------------------------------------------------------
__global__ void prep_kernel(const int* __restrict__ x, const float* __restrict__ hidden,
                            const float* __restrict__ emb,
                            const float* __restrict__ Wf, const float* __restrict__ Uf,
                            const float* __restrict__ Wb, const float* __restrict__ Ub) {
    const long long NUH  = 2LL * G3 * UNITS;              // U fp16 hi
    const long long NWF  = 2LL * 16 * 384 * 32;           // W frags (hi only)
    const long long NEMB = 2LL * VOCAB * EMB;             // emb hi/lo
    const long long NM   = 2LL * NT * NB;
    const long long NH   = 2LL * NB * UNITS;
    const long long NHHF = 2LL * 2 * NB * UNITS;
    const long long total = NUH + NWF + NEMB + NM + NH + NHHF;
    const long long stride = (long long)gridDim.x * blockDim.x;
    for (long long i = (long long)blockIdx.x * blockDim.x + threadIdx.x; i < total; i += stride) {
        if (i < NUH) {
            int dir = (int)(i / ((long long)G3 * UNITS));
            long long r2 = i - (long long)dir * G3 * UNITS;
            int p = (int)(r2 / UNITS);
            int k = (int)(r2 % UNITS);
            const float* U = dir ? Ub : Uf;
            g_uh[dir][p][k] = __float2half(U[(long long)k * G3 + (p % 3) * UNITS + p / 3]);
        } else if (i < NUH + NWF) {
            long long j = i - NUH;
            int dir = (int)(j / (16LL * 384 * 32));
            int r = (int)(j % (16LL * 384 * 32));
            int ks = r / (384 * 32); r %= 384 * 32;
            int pt = r / 32;
            int lane = r % 32;
            int gid = lane >> 2, tig = lane & 3;
            int p = pt * 8 + gid;
            const float* W = dir ? Wb : Wf;
            const long long poff = (long long)(p % 3) * UNITS + p / 3;
            int k0 = ks * 16 + 2 * tig;
            unsigned short b0 = hfbits(__float2half(W[(long long)(k0 + 0) * G3 + poff]));
            unsigned short b1 = hfbits(__float2half(W[(long long)(k0 + 1) * G3 + poff]));
            unsigned short b2 = hfbits(__float2half(W[(long long)(k0 + 8) * G3 + poff]));
            unsigned short b3 = hfbits(__float2half(W[(long long)(k0 + 9) * G3 + poff]));
            g_wbfF[j] = (ull)b0 | ((ull)b1 << 16) | ((ull)b2 << 32) | ((ull)b3 << 48);
        } else if (i < NUH + NWF + NEMB) {
            long long j = i - NUH - NWF;
            int sp = (int)(j / ((long long)VOCAB * EMB));
            long long rem = j - (long long)sp * VOCAB * EMB;
            int e = (int)(rem / EMB), c = (int)(rem % EMB);
            float val = emb[(long long)e * EMB + c];
            __half hi = __float2half(val);
            if (sp == 0) g_embh[0][e][c] = hi;
            else         g_embh[1][e][c] = __float2half(val - __half2float(hi));
        } else if (i < NUH + NWF + NEMB + NM) {
            long long j = i - NUH - NWF - NEMB;
            int dir = (int)(j / (NT * NB));
            int rem = (int)(j % (NT * NB));
            int s = rem / NB, b = rem % NB;
            int t = dir ? (NT - 1 - s) : s;
            g_mask[dir][s][b] = (x[b * NT + t] != 0) ? 1 : 0;
        } else if (i < NUH + NWF + NEMB + NM + NH) {
            long long j = i - NUH - NWF - NEMB - NM;
            int dir = (int)(j / (NB * UNITS));
            int rem = (int)(j % (NB * UNITS));
            int b = rem / UNITS, u = rem % UNITS;
            g_h[dir][0][b][u] = hidden[b * UNITS + u];
        } else {
            long long j = i - NUH - NWF - NEMB - NM - NH;
            int split = (int)(j / (2LL * NB * UNITS));
            long long r1 = j - (long long)split * 2 * NB * UNITS;
            int dir = (int)(r1 / (NB * UNITS));
            int rem = (int)(r1 % (NB * UNITS));
            int b = rem / UNITS, u = rem % UNITS;
            float val = hidden[b * UNITS + u];
            __half hi = __float2half(val);
            if (split == 0) g_hhf[0][dir][0][b][u] = hi;
            else            g_hhf[1][dir][0][b][u] = __float2half(val - __half2float(hi));
        }
    }
    if (blockIdx.x == 0 && threadIdx.x == 0) {
        g_bar_count = 0u; g_bar_gen = 0u;
        g_cnt2[0][0] = 0u; g_cnt2[1][0] = 0u;
        g_gen2[0][0] = 0u; g_gen2[1][0] = 0u;
    }
}

// ---------------- gx via HMMA fp16 2-term: C = xe @ W^T --------------------------------
#define GX_SMEM_BYTES (65536 + 512)
__global__ __launch_bounds__(256) void gx_kernel(const int* __restrict__ x,
                                                 const float* __restrict__ bf_in,
                                                 const float* __restrict__ bb_in) {
    extern __shared__ char smx[];
    const uint32_t smb = smem_u32(smx);
    int* toks = (int*)(smx + 65536);

    const int ct  = blockIdx.x;
    const int t   = blockIdx.y;
    const int dir = blockIdx.z;
    const int tid = threadIdx.x;
    const int wid = tid >> 5;
    const int lane = tid & 31;
    const int mi = wid & 3;
    const int nj = wid >> 2;
    const int gid = lane >> 2;
    const int tig = lane & 3;

    if (tid < 64) {
        int tt = dir ? (NT - 1 - t) : t;
        toks[tid] = x[tid * NT + tt];
    }
    __syncthreads();

    // stage A (xe hi/lo fp16), swizzled 16B granules in 512B rows
#pragma unroll
    for (int j = 0; j < 16; j++) {
        int f = tid + j * 256;
        int sp = f >> 11;
        int rem = f & 2047;
        int row = rem >> 5;
        int seg = rem & 31;
        const void* src = &g_embh[sp][toks[row]][seg * 8];
        uint32_t dst = smb + (uint32_t)sp * 32768u + (uint32_t)(row * 512)
                     + (uint32_t)((seg ^ (row & 7)) << 4);
        CP_ASYNC16(dst, src);
    }
    CP_COMMIT();
    CP_WAIT0();
    __syncthreads();

    float c[4][4];
#pragma unroll
    for (int i = 0; i < 4; i++) { c[i][0] = 0.f; c[i][1] = 0.f; c[i][2] = 0.f; c[i][3] = 0.f; }

    const int arow = mi * 16 + (lane & 15);
    const int acb  = lane >> 4;
    const uint32_t abase = smb + (uint32_t)(arow * 512);
    const ull* wf = g_wbfF + (size_t)dir * 16 * 384 * 32;

#pragma unroll
    for (int ks = 0; ks < 16; ks++) {
        const int seg = ks * 2 + acb;
        const uint32_t sw = (uint32_t)((seg ^ (arow & 7)) << 4);
        uint32_t ah0, ah1, ah2, ah3, al0, al1, al2, al3;
        LDMATRIX_X4(ah0, ah1, ah2, ah3, abase + sw);
        LDMATRIX_X4(al0, al1, al2, al3, abase + 32768u + sw);
        ull vh[4];
#pragma unroll
        for (int ntl = 0; ntl < 4; ntl++)
            vh[ntl] = __ldg(wf + ((size_t)ks * 384 + ct * 8 + nj * 4 + ntl) * 32 + lane);
#pragma unroll
        for (int ntl = 0; ntl < 4; ntl++)
            MMA_F16(c[ntl], ah0, ah1, ah2, ah3, (uint32_t)vh[ntl], (uint32_t)(vh[ntl] >> 32));
#pragma unroll
        for (int ntl = 0; ntl < 4; ntl++)
            MMA_F16(c[ntl], al0, al1, al2, al3, (uint32_t)vh[ntl], (uint32_t)(vh[ntl] >> 32));
    }

    // redistribute C through smem
    __syncthreads();
    float* Cb = (float*)smx;              // [64][68]
    {
        const int r0 = mi * 16 + gid;
#pragma unroll
        for (int ntl = 0; ntl < 4; ntl++) {
            const int col = nj * 32 + ntl * 8 + 2 * tig;
            *(float2*)&Cb[r0 * 68 + col]       = make_float2(c[ntl][0], c[ntl][1]);
            *(float2*)&Cb[(r0 + 8) * 68 + col] = make_float2(c[ntl][2], c[ntl][3]);
        }
    }
    __syncthreads();

    // epilogue: + b_in, write packed gx
    {
        const int b   = tid & 63;
        const int grp = tid >> 6;
        const int pbase = ct * 64;
        const float* bsrc = dir ? bb_in : bf_in;
        float o[16];
#pragma unroll
        for (int q = 0; q < 16; q++) {
            int p = pbase + grp * 16 + q;
            o[q] = Cb[b * 68 + grp * 16 + q] + __ldg(bsrc + (p % 3) * UNITS + p / 3);
        }
        float* gxp = g_gx + ((size_t)(dir * NT + t) * NB + b) * G3 + pbase + grp * 16;
#pragma unroll
        for (int q = 0; q < 4; q++)
            *(float4*)(gxp + q * 4) = *(const float4*)&o[q * 4];
    }
}

// ---------------- persistent HMMA recurrent kernel (fp16 2-term, depth-2 pipe) --------
// U frags: 98304 B | A: 3 slots x 16384 B | bias 192
#define ABUF_OFF    98304u
#define BIAS_OFF    147456u
#define REC_SMEM_BYTES 147648

__global__ __launch_bounds__(256, 1) void recurrent_kernel(const float* __restrict__ bf_rec,
                                                           const float* __restrict__ bb_rec,
                                                           const float* __restrict__ Wp,
                                                           const float* __restrict__ bp,
                                                           float* __restrict__ out) {
    extern __shared__ char smx[];
    const uint32_t smb = smem_u32(smx);

    const int blk   = blockIdx.x;
    const int dir   = blk >> 6;
    const int utile = blk & 63;
    const int pbase = utile * 48;
    const int ubase = utile * 16;
    const int tid  = threadIdx.x;
    const int wid  = tid >> 5;
    const int lane = tid & 31;
    const int mi = wid & 3;
    const int nj = wid >> 2;
    const int gid = lane >> 2;
    const int tig = lane & 3;

    if (tid < 48) {
        const float* brec = dir ? bb_rec : bf_rec;
        ((float*)(smx + BIAS_OFF))[tid] = brec[(tid % 3) * UNITS + ubase + tid / 3];
    }

    // fragment-ordered U (hi only) in smem: [ksg*6 + ntile][lane] x 8B
    for (int e = wid; e < 384; e += 8) {
        int ks = e / 6;
        int nt = e % 6;
        int p  = pbase + nt * 8 + gid;
        const __half* uh = &g_uh[dir][p][ks * 16 + 2 * tig];
        ull v = (ull)(*(const uint32_t*)uh) | ((ull)(*(const uint32_t*)(uh + 8)) << 32);
        *(ull*)(smx + ((size_t)e * 32 + lane) * 8) = v;
    }
    __syncthreads();

    const int b_ep = tid & 63;
    const int usub = tid >> 6;
    const int bar_id = 1 + mi;           // pair barrier id (warps mi and mi+4)

    // per-warp staging: warp loads split nj, rows mi*16..+15, 4 granules/lane
    const int st_row = mi * 16 + (lane >> 1);
    const int st_sega = (lane & 1) * 4;
    const uint32_t st_dst_base = smb + ABUF_OFF + (uint32_t)nj * 8192u
                               + (uint32_t)(st_row * 128);

    for (int s = 0; s < NT; s++) {
        const int pp  = s & 1;
        const int ppn = pp ^ 1;

        float gxv[12];
        {
            const float* gxr = g_gx + ((size_t)(dir * NT + s) * NB + b_ep) * G3 + pbase + usub * 12;
#pragma unroll
            for (int q = 0; q < 3; q++)
                *(float4*)&gxv[q * 4] = __ldcs((const float4*)(gxr + q * 4));
        }
        float hp[4];
        *(float4*)hp = __ldcg((const float4*)(&g_h[dir][pp][b_ep][ubase + usub * 4]));
        const int m = g_mask[dir][s][b_ep];

        const __half* hsrc = &g_hhf[nj][dir][pp][st_row][0];

        // prologue: stage chunks 0 and 1 (slots 0, 1)
#pragma unroll
        for (int pc = 0; pc < 2; pc++) {
            const uint32_t slot_dst = st_dst_base + (uint32_t)pc * 16384u;
            const __half* src = hsrc + pc * 64;
#pragma unroll
            for (int q = 0; q < 4; q++) {
                int seg = st_sega + q;
                CP_ASYNC16(slot_dst + (uint32_t)((seg ^ (st_row & 7)) * 16),
                           src + seg * 8);
            }
            CP_COMMIT();
        }

        float c[3][4];
#pragma unroll
        for (int i = 0; i < 3; i++) { c[i][0] = 0.f; c[i][1] = 0.f; c[i][2] = 0.f; c[i][3] = 0.f; }

        const int arow = mi * 16 + (lane & 15);
        const int acb  = lane >> 4;

        int slot = 0;                     // ci % 3
        int slot2 = 2;                    // (ci+2) % 3
        for (int ci = 0; ci < 16; ci++) {
            if (ci < 15) CP_WAIT1(); else CP_WAIT0();
            NAMED_BAR(bar_id);           // pair: chunk ci staged, ci-1 consumed
            if (ci < 14) {
                const uint32_t slot_dst = st_dst_base + (uint32_t)slot2 * 16384u;
                const __half* src = hsrc + (ci + 2) * 64;
#pragma unroll
                for (int q = 0; q < 4; q++) {
                    int seg = st_sega + q;
                    CP_ASYNC16(slot_dst + (uint32_t)((seg ^ (st_row & 7)) * 16),
                               src + seg * 8);
                }
                CP_COMMIT();
            }
            const uint32_t abase = smb + ABUF_OFF + (uint32_t)slot * 16384u
                                 + (uint32_t)(arow * 128);
#pragma unroll
            for (int ks = 0; ks < 4; ks++) {
                const int seg = ks * 2 + acb;
                const uint32_t sw = (uint32_t)((seg ^ (arow & 7)) * 16);
                uint32_t ah0, ah1, ah2, ah3, al0, al1, al2, al3;
                LDMATRIX_X4(ah0, ah1, ah2, ah3, abase + sw);
                LDMATRIX_X4(al0, al1, al2, al3, abase + 8192u + sw);
                const int ksg = ci * 4 + ks;
                ull vh[3];
#pragma unroll
                for (int ntl = 0; ntl < 3; ntl++)
                    vh[ntl] = *(const ull*)
                        (smx + ((size_t)(ksg * 6 + nj * 3 + ntl) * 32 + lane) * 8);
#pragma unroll
                for (int ntl = 0; ntl < 3; ntl++)
                    MMA_F16(c[ntl], ah0, ah1, ah2, ah3, (uint32_t)vh[ntl], (uint32_t)(vh[ntl] >> 32));
#pragma unroll
                for (int ntl = 0; ntl < 3; ntl++)
                    MMA_F16(c[ntl], al0, al1, al2, al3, (uint32_t)vh[ntl], (uint32_t)(vh[ntl] >> 32));
            }
            slot = (slot == 2) ? 0 : slot + 1;
            slot2 = (slot2 == 2) ? 0 : slot2 + 1;
        }

        // redistribute C through smem (block-wide)
        __syncthreads();
        float* Cb = (float*)(smx + ABUF_OFF);
        {
            const int r0 = mi * 16 + gid;
#pragma unroll
            for (int ntl = 0; ntl < 3; ntl++) {
                const int col = nj * 24 + ntl * 8 + 2 * tig;
                *(float2*)&Cb[r0 * 52 + col]       = make_float2(c[ntl][0], c[ntl][1]);
                *(float2*)&Cb[(r0 + 8) * 52 + col] = make_float2(c[ntl][2], c[ntl][3]);
            }
        }
        __syncthreads();

        // GRU epilogue
        {
            float acc[12];
#pragma unroll
            for (int q = 0; q < 3; q++)
                *(float4*)&acc[q * 4] = *(const float4*)&Cb[b_ep * 52 + usub * 12 + q * 4];
            const float* sb = (const float*)(smx + BIAS_OFF) + usub * 12;
            const int tt = dir ? (NT - 1 - s) : s;

            float hn[4];
            __half hi4[4], lo4[4];
#pragma unroll
            for (int ul = 0; ul < 4; ul++) {
                float z = 1.f / (1.f + expf(-(gxv[ul * 3 + 0] + acc[ul * 3 + 0] + sb[ul * 3 + 0])));
                float r = 1.f / (1.f + expf(-(gxv[ul * 3 + 1] + acc[ul * 3 + 1] + sb[ul * 3 + 1])));
                float hh = tanhf(gxv[ul * 3 + 2] + r * (acc[ul * 3 + 2] + sb[ul * 3 + 2]));
                float v = z * hp[ul] + (1.f - z) * hh;
                if (!m) v = hp[ul];
                hn[ul] = v;
                __half hi = __float2half(v);
                hi4[ul] = hi;
                lo4[ul] = __float2half(v - __half2float(hi));
            }
            const int uo = ubase + usub * 4;
            *(float4*)(out + ((size_t)b_ep * NT + tt) * (2 * UNITS) + dir * UNITS + uo)
                = *(const float4*)hn;
            *(float4*)(&g_h[dir][ppn][b_ep][uo]) = *(const float4*)hn;
            *(uint2*)(&g_hhf[0][dir][ppn][b_ep][uo]) = *(const uint2*)hi4;
            *(uint2*)(&g_hhf[1][dir][ppn][b_ep][uo]) = *(const uint2*)lo4;
        }

        barrier_generic(&g_cnt2[dir][0], &g_gen2[dir][0], 64u, (unsigned)(s + 1));
    }

    // full barrier before cross-dir final state
    barrier_generic(&g_bar_count, &g_bar_gen, 128u, 1u);

    // fused final state: tanh(concat(hf,hb) @ Wp + bp), final h in pingpong buffer 0
    {
        float* sst = (float*)smx;
        const int tx8 = tid & 7;
        const int tyS = tid >> 3;
        const int b0 = tyS * 2;
        const int ocol = blk * 8 + tx8;
        const float* wp = Wp + ocol;
        float acc0 = 0.f, acc1 = 0.f;
        for (int k0 = 0; k0 < 2 * UNITS; k0 += 128) {
            __syncthreads();
#pragma unroll
            for (int j = 0; j < 8; j++) {
                int f = tid + j * 256;
                int b = f >> 5;
                int k4 = (f & 31) << 2;
                int gk = k0 + k4;
                float4 v = __ldcg((const float4*)(&g_h[gk >> 10][0][b][gk & 1023]));
                *(float4*)&sst[b * 132 + k4] = v;
            }
            __syncthreads();
#pragma unroll 8
            for (int kk = 0; kk < 128; kk++) {
                float w = __ldg(wp + (size_t)(k0 + kk) * UNITS);
                acc0 = fmaf(sst[b0 * 132 + kk], w, acc0);
                acc1 = fmaf(sst[(b0 + 1) * 132 + kk], w, acc1);
            }
        }
        float bpv = bp[ocol];
        const size_t so = (size_t)NB * NT * (2 * UNITS);
        out[so + (size_t)b0 * UNITS + ocol]       = tanhf(acc0 + bpv);
        out[so + (size_t)(b0 + 1) * UNITS + ocol] = tanhf(acc1 + bpv);
    }
}

// ---------------- launch --------------------------------------------------------------
extern "C" void kernel_launch(void* const* d_in, const int* in_sizes, int n_in,
                              void* d_out, int out_size) {
    (void)in_sizes; (void)n_in; (void)out_size;
    const int*   x      = (const int*)  d_in[0];
    const float* hidden = (const float*)d_in[1];
    const float* emb    = (const float*)d_in[2];
    const float* Wf     = (const float*)d_in[3];
    const float* Uf     = (const float*)d_in[4];
    const float* bf_in  = (const float*)d_in[5];
    const float* bf_rec = (const float*)d_in[6];
    const float* Wb     = (const float*)d_in[7];
    const float* Ub     = (const float*)d_in[8];
    const float* bb_in  = (const float*)d_in[9];
    const float* bb_rec = (const float*)d_in[10];
    const float* Wp     = (const float*)d_in[11];
    const float* bp     = (const float*)d_in[12];
    float* out = (float*)d_out;

    cudaFuncSetAttribute(recurrent_kernel,
                         cudaFuncAttributeMaxDynamicSharedMemorySize, REC_SMEM_BYTES);
    cudaFuncSetAttribute(gx_kernel,
                         cudaFuncAttributeMaxDynamicSharedMemorySize, GX_SMEM_BYTES);

    prep_kernel<<<4096, 256>>>(x, hidden, emb, Wf, Uf, Wb, Ub);
    dim3 ggx(48, NT, 2);
    gx_kernel<<<ggx, 256, GX_SMEM_BYTES>>>(x, bf_in, bb_in);
    recurrent_kernel<<<REC_BLOCKS, 256, REC_SMEM_BYTES>>>(bf_rec, bb_rec, Wp, bp, out);
}

// round 16
// speedup vs baseline: 1.3330x; 1.0024x over previous
#include <cuda_runtime.h>
#include <cuda_fp16.h>
#include <cstdint>
#include <math.h>

#define VOCAB 32000
#define EMB   256
#define UNITS 1024
#define NB    64
#define NT    256
#define G3    3072
#define REC_BLOCKS 128

typedef unsigned long long ull;

// ---------------- device scratch ---------------------------------------------------
__device__ float g_gx[(size_t)2 * NT * NB * G3];         // packed gate-major inputs
__device__ __half g_uh[2][G3][UNITS];                    // [dir][p][k] U^T fp16 (hi only)
__device__ ull  g_wbfF[2 * 16 * 384 * 32];               // W frags fp16-hi [dir][ks][pt][lane]
__device__ __half g_embh[2][VOCAB][EMB];                 // emb fp16 hi/lo
__device__ float g_h [2][NB][UNITS];                     // fp32 h (final state only)
__device__ __half g_hhf[2][2][2][NB][UNITS];             // [split][dir][pp][b][u] fp16
__device__ unsigned char g_mask[2][NT][NB];
__device__ unsigned g_bar_count;
__device__ unsigned g_bar_gen;
__device__ unsigned g_leaf[2][8][32];                    // two-level barrier: leaf counters
__device__ unsigned g_root[2][32];
__device__ unsigned g_gen2[2][32];

// ---------------- helpers -----------------------------------------------------------
__device__ __forceinline__ uint32_t smem_u32(const void* p) {
    uint32_t a;
    asm("{ .reg .u64 t; cvta.to.shared.u64 t, %1; cvt.u32.u64 %0, t; }" : "=r"(a) : "l"(p));
    return a;
}
__device__ __forceinline__ unsigned short hfbits(__half v) {
    return *(unsigned short*)&v;
}
__device__ __forceinline__ float sigmoid_fast(float x) {
    float e = __expf(-x);
    return __fdividef(1.f, 1.f + e);
}
__device__ __forceinline__ float tanh_fast(float x) {
    float r;
    asm("tanh.approx.f32 %0, %1;" : "=f"(r) : "f"(x));
    return r;
}

#define CP_ASYNC16(dst, src) \
    asm volatile("cp.async.cg.shared.global [%0], [%1], 16;" :: "r"(dst), "l"(src) : "memory")
#define CP_COMMIT() asm volatile("cp.async.commit_group;" ::: "memory")
#define CP_WAIT0()  asm volatile("cp.async.wait_group 0;" ::: "memory")
#define CP_WAIT1()  asm volatile("cp.async.wait_group 1;" ::: "memory")
#define NAMED_BAR(id) asm volatile("bar.sync %0, 64;" :: "r"(id) : "memory")

#define LDMATRIX_X4(r0, r1, r2, r3, addr) \
    asm volatile("ldmatrix.sync.aligned.m8n8.x4.shared.b16 {%0,%1,%2,%3}, [%4];" \
                 : "=r"(r0), "=r"(r1), "=r"(r2), "=r"(r3) : "r"(addr))

#define MMA_F16(c, a0, a1, a2, a3, b0, b1) \
    asm volatile("mma.sync.aligned.m16n8k16.row.col.f32.f16.f16.f32 " \
                 "{%0,%1,%2,%3}, {%4,%5,%6,%7}, {%8,%9}, {%0,%1,%2,%3};" \
                 : "+f"((c)[0]), "+f"((c)[1]), "+f"((c)[2]), "+f"((c)[3]) \
                 : "r"(a0), "r"(a1), "r"(a2), "r"(a3), "r"(b0), "r"(b1))

__device__ __forceinline__ void barrier_generic(unsigned* cnt, unsigned* gen,
                                                unsigned nblk, unsigned target) {
    __syncthreads();
    if (threadIdx.x == 0) {
        unsigned prev;
        asm volatile("atom.acq_rel.gpu.add.u32 %0, [%1], 1;"
                     : "=r"(prev) : "l"(cnt) : "memory");
        if (prev == target * nblk - 1u) {
            asm volatile("st.release.gpu.u32 [%0], %1;"
                         :: "l"(gen), "r"(target) : "memory");
        } else {
            unsigned g;
            do {
                asm volatile("ld.acquire.gpu.u32 %0, [%1];"
                             : "=r"(g) : "l"(gen) : "memory");
            } while (g < target);
        }
    }
    __syncthreads();
}

// two-level per-dir barrier: 8 leaves x 8 blocks, then root, then gen release
__device__ __forceinline__ void barrier_2level(int dir, int leaf, unsigned target) {
    __syncthreads();
    if (threadIdx.x == 0) {
        unsigned prev;
        asm volatile("atom.acq_rel.gpu.add.u32 %0, [%1], 1;"
                     : "=r"(prev) : "l"(&g_leaf[dir][leaf][0]) : "memory");
        if (prev == target * 8u - 1u) {
            unsigned prevr;
            asm volatile("atom.acq_rel.gpu.add.u32 %0, [%1], 1;"
                         : "=r"(prevr) : "l"(&g_root[dir][0]) : "memory");
            if (prevr == target * 8u - 1u) {
                asm volatile("st.release.gpu.u32 [%0], %1;"
                             :: "l"(&g_gen2[dir][0]), "r"(target) : "memory");
            }
        }
        unsigned g;
        do {
            asm volatile("ld.acquire.gpu.u32 %0, [%1];"
                         : "=r"(g) : "l"(&g_gen2[dir][0]) : "memory");
        } while (g < target);
    }
    __syncthreads();
}

// ---------------- prep ---------------------------------------------------------------
__global__ void prep_kernel(const int* __restrict__ x, const float* __restrict__ hidden,
                            const float* __restrict__ emb,
                            const float* __restrict__ Wf, const float* __restrict__ Uf,
                            const float* __restrict__ Wb, const float* __restrict__ Ub) {
    const long long NUH  = 2LL * G3 * UNITS;              // U fp16 hi
    const long long NWF  = 2LL * 16 * 384 * 32;           // W frags (hi only)
    const long long NEMB = 2LL * VOCAB * EMB;             // emb hi/lo
    const long long NM   = 2LL * NT * NB;
    const long long NH   = 2LL * NB * UNITS;
    const long long NHHF = 2LL * 2 * NB * UNITS;
    const long long total = NUH + NWF + NEMB + NM + NH + NHHF;
    const long long stride = (long long)gridDim.x * blockDim.x;
    for (long long i = (long long)blockIdx.x * blockDim.x + threadIdx.x; i < total; i += stride) {
        if (i < NUH) {
            int dir = (int)(i / ((long long)G3 * UNITS));
            long long r2 = i - (long long)dir * G3 * UNITS;
            int p = (int)(r2 / UNITS);
            int k = (int)(r2 % UNITS);
            const float* U = dir ? Ub : Uf;
            g_uh[dir][p][k] = __float2half(U[(long long)k * G3 + (p % 3) * UNITS + p / 3]);
        } else if (i < NUH + NWF) {
            long long j = i - NUH;
            int dir = (int)(j / (16LL * 384 * 32));
            int r = (int)(j % (16LL * 384 * 32));
            int ks = r / (384 * 32); r %= 384 * 32;
            int pt = r / 32;
            int lane = r % 32;
            int gid = lane >> 2, tig = lane & 3;
            int p = pt * 8 + gid;
            const float* W = dir ? Wb : Wf;
            const long long poff = (long long)(p % 3) * UNITS + p / 3;
            int k0 = ks * 16 + 2 * tig;
            unsigned short b0 = hfbits(__float2half(W[(long long)(k0 + 0) * G3 + poff]));
            unsigned short b1 = hfbits(__float2half(W[(long long)(k0 + 1) * G3 + poff]));
            unsigned short b2 = hfbits(__float2half(W[(long long)(k0 + 8) * G3 + poff]));
            unsigned short b3 = hfbits(__float2half(W[(long long)(k0 + 9) * G3 + poff]));
            g_wbfF[j] = (ull)b0 | ((ull)b1 << 16) | ((ull)b2 << 32) | ((ull)b3 << 48);
        } else if (i < NUH + NWF + NEMB) {
            long long j = i - NUH - NWF;
            int sp = (int)(j / ((long long)VOCAB * EMB));
            long long rem = j - (long long)sp * VOCAB * EMB;
            int e = (int)(rem / EMB), c = (int)(rem % EMB);
            float val = emb[(long long)e * EMB + c];
            __half hi = __float2half(val);
            if (sp == 0) g_embh[0][e][c] = hi;
            else         g_embh[1][e][c] = __float2half(val - __half2float(hi));
        } else if (i < NUH + NWF + NEMB + NM) {
            long long j = i - NUH - NWF - NEMB;
            int dir = (int)(j / (NT * NB));
            int rem = (int)(j % (NT * NB));
            int s = rem / NB, b = rem % NB;
            int t = dir ? (NT - 1 - s) : s;
            g_mask[dir][s][b] = (x[b * NT + t] != 0) ? 1 : 0;
        } else if (i < NUH + NWF + NEMB + NM + NH) {
            long long j = i - NUH - NWF - NEMB - NM;
            int dir = (int)(j / (NB * UNITS));
            int rem = (int)(j % (NB * UNITS));
            int b = rem / UNITS, u = rem % UNITS;
            g_h[dir][b][u] = hidden[b * UNITS + u];
        } else {
            long long j = i - NUH - NWF - NEMB - NM - NH;
            int split = (int)(j / (2LL * NB * UNITS));
            long long r1 = j - (long long)split * 2 * NB * UNITS;
            int dir = (int)(r1 / (NB * UNITS));
            int rem = (int)(r1 % (NB * UNITS));
            int b = rem / UNITS, u = rem % UNITS;
            float val = hidden[b * UNITS + u];
            __half hi = __float2half(val);
            if (split == 0) g_hhf[0][dir][0][b][u] = hi;
            else            g_hhf[1][dir][0][b][u] = __float2half(val - __half2float(hi));
        }
    }
    if (blockIdx.x == 0 && threadIdx.x == 0) {
        g_bar_count = 0u; g_bar_gen = 0u;
        for (int d = 0; d < 2; d++) {
            g_root[d][0] = 0u; g_gen2[d][0] = 0u;
            for (int l = 0; l < 8; l++) g_leaf[d][l][0] = 0u;
        }
    }
}

// ---------------- gx via HMMA fp16 2-term: C = xe @ W^T --------------------------------
#define GX_SMEM_BYTES (65536 + 512)
__global__ __launch_bounds__(256) void gx_kernel(const int* __restrict__ x,
                                                 const float* __restrict__ bf_in,
                                                 const float* __restrict__ bb_in) {
    extern __shared__ char smx[];
    const uint32_t smb = smem_u32(smx);
    int* toks = (int*)(smx + 65536);

    const int ct  = blockIdx.x;
    const int t   = blockIdx.y;
    const int dir = blockIdx.z;
    const int tid = threadIdx.x;
    const int wid = tid >> 5;
    const int lane = tid & 31;
    const int mi = wid & 3;
    const int nj = wid >> 2;
    const int gid = lane >> 2;
    const int tig = lane & 3;

    if (tid < 64) {
        int tt = dir ? (NT - 1 - t) : t;
        toks[tid] = x[tid * NT + tt];
    }
    __syncthreads();

    // stage A (xe hi/lo fp16), swizzled 16B granules in 512B rows
#pragma unroll
    for (int j = 0; j < 16; j++) {
        int f = tid + j * 256;
        int sp = f >> 11;
        int rem = f & 2047;
        int row = rem >> 5;
        int seg = rem & 31;
        const void* src = &g_embh[sp][toks[row]][seg * 8];
        uint32_t dst = smb + (uint32_t)sp * 32768u + (uint32_t)(row * 512)
                     + (uint32_t)((seg ^ (row & 7)) << 4);
        CP_ASYNC16(dst, src);
    }
    CP_COMMIT();
    CP_WAIT0();
    __syncthreads();

    float c[4][4];
#pragma unroll
    for (int i = 0; i < 4; i++) { c[i][0] = 0.f; c[i][1] = 0.f; c[i][2] = 0.f; c[i][3] = 0.f; }

    const int arow = mi * 16 + (lane & 15);
    const int acb  = lane >> 4;
    const uint32_t abase = smb + (uint32_t)(arow * 512);
    const ull* wf = g_wbfF + (size_t)dir * 16 * 384 * 32;

#pragma unroll
    for (int ks = 0; ks < 16; ks++) {
        const int seg = ks * 2 + acb;
        const uint32_t sw = (uint32_t)((seg ^ (arow & 7)) << 4);
        uint32_t ah0, ah1, ah2, ah3, al0, al1, al2, al3;
        LDMATRIX_X4(ah0, ah1, ah2, ah3, abase + sw);
        LDMATRIX_X4(al0, al1, al2, al3, abase + 32768u + sw);
        ull vh[4];
#pragma unroll
        for (int ntl = 0; ntl < 4; ntl++)
            vh[ntl] = __ldg(wf + ((size_t)ks * 384 + ct * 8 + nj * 4 + ntl) * 32 + lane);
#pragma unroll
        for (int ntl = 0; ntl < 4; ntl++)
            MMA_F16(c[ntl], ah0, ah1, ah2, ah3, (uint32_t)vh[ntl], (uint32_t)(vh[ntl] >> 32));
#pragma unroll
        for (int ntl = 0; ntl < 4; ntl++)
            MMA_F16(c[ntl], al0, al1, al2, al3, (uint32_t)vh[ntl], (uint32_t)(vh[ntl] >> 32));
    }

    // redistribute C through smem
    __syncthreads();
    float* Cb = (float*)smx;              // [64][68]
    {
        const int r0 = mi * 16 + gid;
#pragma unroll
        for (int ntl = 0; ntl < 4; ntl++) {
            const int col = nj * 32 + ntl * 8 + 2 * tig;
            *(float2*)&Cb[r0 * 68 + col]       = make_float2(c[ntl][0], c[ntl][1]);
            *(float2*)&Cb[(r0 + 8) * 68 + col] = make_float2(c[ntl][2], c[ntl][3]);
        }
    }
    __syncthreads();

    // epilogue: + b_in, write packed gx
    {
        const int b   = tid & 63;
        const int grp = tid >> 6;
        const int pbase = ct * 64;
        const float* bsrc = dir ? bb_in : bf_in;
        float o[16];
#pragma unroll
        for (int q = 0; q < 16; q++) {
            int p = pbase + grp * 16 + q;
            o[q] = Cb[b * 68 + grp * 16 + q] + __ldg(bsrc + (p % 3) * UNITS + p / 3);
        }
        float* gxp = g_gx + ((size_t)(dir * NT + t) * NB + b) * G3 + pbase + grp * 16;
#pragma unroll
        for (int q = 0; q < 4; q++)
            *(float4*)(gxp + q * 4) = *(const float4*)&o[q * 4];
    }
}

// ---------------- persistent HMMA recurrent kernel (fp16 2-term, depth-2 pipe) --------
// U frags: 98304 B | A: 3 slots x 16384 B | bias 192
#define ABUF_OFF    98304u
#define BIAS_OFF    147456u
#define REC_SMEM_BYTES 147648

__global__ __launch_bounds__(256, 1) void recurrent_kernel(const float* __restrict__ bf_rec,
                                                           const float* __restrict__ bb_rec,
                                                           const float* __restrict__ Wp,
                                                           const float* __restrict__ bp,
                                                           float* __restrict__ out) {
    extern __shared__ char smx[];
    const uint32_t smb = smem_u32(smx);

    const int blk   = blockIdx.x;
    const int dir   = blk >> 6;
    const int utile = blk & 63;
    const int pbase = utile * 48;
    const int ubase = utile * 16;
    const int tid  = threadIdx.x;
    const int wid  = tid >> 5;
    const int lane = tid & 31;
    const int mi = wid & 3;
    const int nj = wid >> 2;
    const int gid = lane >> 2;
    const int tig = lane & 3;
    const int leaf = utile >> 3;

    if (tid < 48) {
        const float* brec = dir ? bb_rec : bf_rec;
        ((float*)(smx + BIAS_OFF))[tid] = brec[(tid % 3) * UNITS + ubase + tid / 3];
    }

    // fragment-ordered U (hi only) in smem: [ksg*6 + ntile][lane] x 8B
    for (int e = wid; e < 384; e += 8) {
        int ks = e / 6;
        int nt = e % 6;
        int p  = pbase + nt * 8 + gid;
        const __half* uh = &g_uh[dir][p][ks * 16 + 2 * tig];
        ull v = (ull)(*(const uint32_t*)uh) | ((ull)(*(const uint32_t*)(uh + 8)) << 32);
        *(ull*)(smx + ((size_t)e * 32 + lane) * 8) = v;
    }
    __syncthreads();

    const int b_ep = tid & 63;
    const int usub = tid >> 6;
    const int bar_id = 1 + mi;           // pair barrier id (warps mi and mi+4)

    // per-warp staging: warp loads split nj, rows mi*16..+15, 4 granules/lane
    const int st_row = mi * 16 + (lane >> 1);
    const int st_sega = (lane & 1) * 4;
    const uint32_t st_dst_base = smb + ABUF_OFF + (uint32_t)nj * 8192u
                               + (uint32_t)(st_row * 128);

    // h carried in registers across steps (this thread wrote exactly these values)
    float hp[4];
    *(float4*)hp = *(const float4*)(&g_h[dir][b_ep][ubase + usub * 4]);

    for (int s = 0; s < NT; s++) {
        const int pp  = s & 1;
        const int ppn = pp ^ 1;

        float gxv[12];
        {
            const float* gxr = g_gx + ((size_t)(dir * NT + s) * NB + b_ep) * G3 + pbase + usub * 12;
#pragma unroll
            for (int q = 0; q < 3; q++)
                *(float4*)&gxv[q * 4] = __ldcs((const float4*)(gxr + q * 4));
        }
        const int m = g_mask[dir][s][b_ep];

        const __half* hsrc = &g_hhf[nj][dir][pp][st_row][0];

        // prologue: stage chunks 0 and 1 (slots 0, 1)
#pragma unroll
        for (int pc = 0; pc < 2; pc++) {
            const uint32_t slot_dst = st_dst_base + (uint32_t)pc * 16384u;
            const __half* src = hsrc + pc * 64;
#pragma unroll
            for (int q = 0; q < 4; q++) {
                int seg = st_sega + q;
                CP_ASYNC16(slot_dst + (uint32_t)((seg ^ (st_row & 7)) * 16),
                           src + seg * 8);
            }
            CP_COMMIT();
        }

        float c[3][4];
#pragma unroll
        for (int i = 0; i < 3; i++) { c[i][0] = 0.f; c[i][1] = 0.f; c[i][2] = 0.f; c[i][3] = 0.f; }

        const int arow = mi * 16 + (lane & 15);
        const int acb  = lane >> 4;

        int slot = 0;                     // ci % 3
        int slot2 = 2;                    // (ci+2) % 3
        for (int ci = 0; ci < 16; ci++) {
            if (ci < 15) CP_WAIT1(); else CP_WAIT0();
            NAMED_BAR(bar_id);           // pair: chunk ci staged, ci-1 consumed
            if (ci < 14) {
                const uint32_t slot_dst = st_dst_base + (uint32_t)slot2 * 16384u;
                const __half* src = hsrc + (ci + 2) * 64;
#pragma unroll
                for (int q = 0; q < 4; q++) {
                    int seg = st_sega + q;
                    CP_ASYNC16(slot_dst + (uint32_t)((seg ^ (st_row & 7)) * 16),
                               src + seg * 8);
                }
                CP_COMMIT();
            }
            const uint32_t abase = smb + ABUF_OFF + (uint32_t)slot * 16384u
                                 + (uint32_t)(arow * 128);
#pragma unroll
            for (int ks = 0; ks < 4; ks++) {
                const int seg = ks * 2 + acb;
                const uint32_t sw = (uint32_t)((seg ^ (arow & 7)) * 16);
                uint32_t ah0, ah1, ah2, ah3, al0, al1, al2, al3;
                LDMATRIX_X4(ah0, ah1, ah2, ah3, abase + sw);
                LDMATRIX_X4(al0, al1, al2, al3, abase + 8192u + sw);
                const int ksg = ci * 4 + ks;
                ull vh[3];
#pragma unroll
                for (int ntl = 0; ntl < 3; ntl++)
                    vh[ntl] = *(const ull*)
                        (smx + ((size_t)(ksg * 6 + nj * 3 + ntl) * 32 + lane) * 8);
#pragma unroll
                for (int ntl = 0; ntl < 3; ntl++)
                    MMA_F16(c[ntl], ah0, ah1, ah2, ah3, (uint32_t)vh[ntl], (uint32_t)(vh[ntl] >> 32));
#pragma unroll
                for (int ntl = 0; ntl < 3; ntl++)
                    MMA_F16(c[ntl], al0, al1, al2, al3, (uint32_t)vh[ntl], (uint32_t)(vh[ntl] >> 32));
            }
            slot = (slot == 2) ? 0 : slot + 1;
            slot2 = (slot2 == 2) ? 0 : slot2 + 1;
        }

        // redistribute C through smem (block-wide)
        __syncthreads();
        float* Cb = (float*)(smx + ABUF_OFF);
        {
            const int r0 = mi * 16 + gid;
#pragma unroll
            for (int ntl = 0; ntl < 3; ntl++) {
                const int col = nj * 24 + ntl * 8 + 2 * tig;
                *(float2*)&Cb[r0 * 52 + col]       = make_float2(c[ntl][0], c[ntl][1]);
                *(float2*)&Cb[(r0 + 8) * 52 + col] = make_float2(c[ntl][2], c[ntl][3]);
            }
        }
        __syncthreads();

        // GRU epilogue (fast transcendentals, h in registers)
        {
            float acc[12];
#pragma unroll
            for (int q = 0; q < 3; q++)
                *(float4*)&acc[q * 4] = *(const float4*)&Cb[b_ep * 52 + usub * 12 + q * 4];
            const float* sb = (const float*)(smx + BIAS_OFF) + usub * 12;
            const int tt = dir ? (NT - 1 - s) : s;

            float hn[4];
            __half hi4[4], lo4[4];
#pragma unroll
            for (int ul = 0; ul < 4; ul++) {
                float z = sigmoid_fast(gxv[ul * 3 + 0] + acc[ul * 3 + 0] + sb[ul * 3 + 0]);
                float r = sigmoid_fast(gxv[ul * 3 + 1] + acc[ul * 3 + 1] + sb[ul * 3 + 1]);
                float hh = tanh_fast(gxv[ul * 3 + 2] + r * (acc[ul * 3 + 2] + sb[ul * 3 + 2]));
                float v = z * hp[ul] + (1.f - z) * hh;
                if (!m) v = hp[ul];
                hn[ul] = v;
                __half hi = __float2half(v);
                hi4[ul] = hi;
                lo4[ul] = __float2half(v - __half2float(hi));
            }
            const int uo = ubase + usub * 4;
            *(float4*)(out + ((size_t)b_ep * NT + tt) * (2 * UNITS) + dir * UNITS + uo)
                = *(const float4*)hn;
            *(uint2*)(&g_hhf[0][dir][ppn][b_ep][uo]) = *(const uint2*)hi4;
            *(uint2*)(&g_hhf[1][dir][ppn][b_ep][uo]) = *(const uint2*)lo4;
#pragma unroll
            for (int ul = 0; ul < 4; ul++) hp[ul] = hn[ul];
            if (s == NT - 1)
                *(float4*)(&g_h[dir][b_ep][uo]) = *(const float4*)hn;
        }

        barrier_2level(dir, leaf, (unsigned)(s + 1));
    }

    // full barrier before cross-dir final state
    barrier_generic(&g_bar_count, &g_bar_gen, 128u, 1u);

    // fused final state: tanh(concat(hf,hb) @ Wp + bp)
    {
        float* sst = (float*)smx;
        const int tx8 = tid & 7;
        const int tyS = tid >> 3;
        const int b0 = tyS * 2;
        const int ocol = blk * 8 + tx8;
        const float* wp = Wp + ocol;
        float acc0 = 0.f, acc1 = 0.f;
        for (int k0 = 0; k0 < 2 * UNITS; k0 += 128) {
            __syncthreads();
#pragma unroll
            for (int j = 0; j < 8; j++) {
                int f = tid + j * 256;
                int b = f >> 5;
                int k4 = (f & 31) << 2;
                int gk = k0 + k4;
                float4 v = __ldcg((const float4*)(&g_h[gk >> 10][b][gk & 1023]));
                *(float4*)&sst[b * 132 + k4] = v;
            }
            __syncthreads();
#pragma unroll 8
            for (int kk = 0; kk < 128; kk++) {
                float w = __ldg(wp + (size_t)(k0 + kk) * UNITS);
                acc0 = fmaf(sst[b0 * 132 + kk], w, acc0);
                acc1 = fmaf(sst[(b0 + 1) * 132 + kk], w, acc1);
            }
        }
        float bpv = bp[ocol];
        const size_t so = (size_t)NB * NT * (2 * UNITS);
        out[so + (size_t)b0 * UNITS + ocol]       = tanhf(acc0 + bpv);
        out[so + (size_t)(b0 + 1) * UNITS + ocol] = tanhf(acc1 + bpv);
    }
}

// ---------------- launch --------------------------------------------------------------
extern "C" void kernel_launch(void* const* d_in, const int* in_sizes, int n_in,
                              void* d_out, int out_size) {
    (void)in_sizes; (void)n_in; (void)out_size;
    const int*   x      = (const int*)  d_in[0];
    const float* hidden = (const float*)d_in[1];
    const float* emb    = (const float*)d_in[2];
    const float* Wf     = (const float*)d_in[3];
    const float* Uf     = (const float*)d_in[4];
    const float* bf_in  = (const float*)d_in[5];
    const float* bf_rec = (const float*)d_in[6];
    const float* Wb     = (const float*)d_in[7];
    const float* Ub     = (const float*)d_in[8];
    const float* bb_in  = (const float*)d_in[9];
    const float* bb_rec = (const float*)d_in[10];
    const float* Wp     = (const float*)d_in[11];
    const float* bp     = (const float*)d_in[12];
    float* out = (float*)d_out;

    cudaFuncSetAttribute(recurrent_kernel,
                         cudaFuncAttributeMaxDynamicSharedMemorySize, REC_SMEM_BYTES);
    cudaFuncSetAttribute(gx_kernel,
                         cudaFuncAttributeMaxDynamicSharedMemorySize, GX_SMEM_BYTES);

    prep_kernel<<<4096, 256>>>(x, hidden, emb, Wf, Uf, Wb, Ub);
    dim3 ggx(48, NT, 2);
    gx_kernel<<<ggx, 256, GX_SMEM_BYTES>>>(x, bf_in, bb_in);
    recurrent_kernel<<<REC_BLOCKS, 256, REC_SMEM_BYTES>>>(bf_rec, bb_rec, Wp, bp, out);
}

// round 17
// speedup vs baseline: 1.6645x; 1.2487x over previous
#include <cuda_runtime.h>
#include <cuda_fp16.h>
#include <cstdint>
#include <math.h>

#define VOCAB 32000
#define EMB   256
#define UNITS 1024
#define NB    64
#define NT    256
#define G3    3072
#define REC_BLOCKS 128

typedef unsigned long long ull;

// ---------------- device scratch ---------------------------------------------------
__device__ float g_gx[(size_t)2 * NT * NB * G3];         // packed gate-major inputs
__device__ __half g_uh[2][G3][UNITS];                    // [dir][p][k] U^T fp16 (hi only)
__device__ ull  g_wbfF[2 * 16 * 384 * 32];               // W frags fp16-hi [dir][ks][pt][lane]
__device__ __half g_embh[2][VOCAB][EMB];                 // emb fp16 hi/lo
__device__ float g_h [2][NB][UNITS];                     // fp32 h (final state only)
__device__ __half g_hhf[2][2][NB][UNITS];                // [dir][pp][b][u] fp16 (hi only)
__device__ unsigned char g_mask[2][NT][NB];
__device__ unsigned g_bar_count;
__device__ unsigned g_bar_gen;
__device__ unsigned g_leaf[2][8][32];                    // two-level barrier: leaf counters
__device__ unsigned g_root[2][32];
__device__ unsigned g_gen2[2][32];

// ---------------- helpers -----------------------------------------------------------
__device__ __forceinline__ uint32_t smem_u32(const void* p) {
    uint32_t a;
    asm("{ .reg .u64 t; cvta.to.shared.u64 t, %1; cvt.u32.u64 %0, t; }" : "=r"(a) : "l"(p));
    return a;
}
__device__ __forceinline__ unsigned short hfbits(__half v) {
    return *(unsigned short*)&v;
}
__device__ __forceinline__ float sigmoid_fast(float x) {
    float e = __expf(-x);
    return __fdividef(1.f, 1.f + e);
}
__device__ __forceinline__ float tanh_fast(float x) {
    float r;
    asm("tanh.approx.f32 %0, %1;" : "=f"(r) : "f"(x));
    return r;
}

#define CP_ASYNC16(dst, src) \
    asm volatile("cp.async.cg.shared.global [%0], [%1], 16;" :: "r"(dst), "l"(src) : "memory")
#define CP_COMMIT() asm volatile("cp.async.commit_group;" ::: "memory")
#define CP_WAIT0()  asm volatile("cp.async.wait_group 0;" ::: "memory")
#define CP_WAIT1()  asm volatile("cp.async.wait_group 1;" ::: "memory")
#define NAMED_BAR(id) asm volatile("bar.sync %0, 64;" :: "r"(id) : "memory")

#define LDMATRIX_X4(r0, r1, r2, r3, addr) \
    asm volatile("ldmatrix.sync.aligned.m8n8.x4.shared.b16 {%0,%1,%2,%3}, [%4];" \
                 : "=r"(r0), "=r"(r1), "=r"(r2), "=r"(r3) : "r"(addr))

#define MMA_F16(c, a0, a1, a2, a3, b0, b1) \
    asm volatile("mma.sync.aligned.m16n8k16.row.col.f32.f16.f16.f32 " \
                 "{%0,%1,%2,%3}, {%4,%5,%6,%7}, {%8,%9}, {%0,%1,%2,%3};" \
                 : "+f"((c)[0]), "+f"((c)[1]), "+f"((c)[2]), "+f"((c)[3]) \
                 : "r"(a0), "r"(a1), "r"(a2), "r"(a3), "r"(b0), "r"(b1))

__device__ __forceinline__ void barrier_generic(unsigned* cnt, unsigned* gen,
                                                unsigned nblk, unsigned target) {
    __syncthreads();
    if (threadIdx.x == 0) {
        unsigned prev;
        asm volatile("atom.acq_rel.gpu.add.u32 %0, [%1], 1;"
                     : "=r"(prev) : "l"(cnt) : "memory");
        if (prev == target * nblk - 1u) {
            asm volatile("st.release.gpu.u32 [%0], %1;"
                         :: "l"(gen), "r"(target) : "memory");
        } else {
            unsigned g;
            do {
                asm volatile("ld.acquire.gpu.u32 %0, [%1];"
                             : "=r"(g) : "l"(gen) : "memory");
            } while (g < target);
        }
    }
    __syncthreads();
}

// two-level per-dir barrier: 8 leaves x 8 blocks, then root, then gen release
__device__ __forceinline__ void barrier_2level(int dir, int leaf, unsigned target) {
    __syncthreads();
    if (threadIdx.x == 0) {
        unsigned prev;
        asm volatile("atom.acq_rel.gpu.add.u32 %0, [%1], 1;"
                     : "=r"(prev) : "l"(&g_leaf[dir][leaf][0]) : "memory");
        if (prev == target * 8u - 1u) {
            unsigned prevr;
            asm volatile("atom.acq_rel.gpu.add.u32 %0, [%1], 1;"
                         : "=r"(prevr) : "l"(&g_root[dir][0]) : "memory");
            if (prevr == target * 8u - 1u) {
                asm volatile("st.release.gpu.u32 [%0], %1;"
                             :: "l"(&g_gen2[dir][0]), "r"(target) : "memory");
            }
        }
        unsigned g;
        do {
            asm volatile("ld.acquire.gpu.u32 %0, [%1];"
                         : "=r"(g) : "l"(&g_gen2[dir][0]) : "memory");
        } while (g < target);
    }
    __syncthreads();
}

// ---------------- prep ---------------------------------------------------------------
__global__ void prep_kernel(const int* __restrict__ x, const float* __restrict__ hidden,
                            const float* __restrict__ emb,
                            const float* __restrict__ Wf, const float* __restrict__ Uf,
                            const float* __restrict__ Wb, const float* __restrict__ Ub) {
    const long long NUH  = 2LL * G3 * UNITS;              // U fp16 hi
    const long long NWF  = 2LL * 16 * 384 * 32;           // W frags (hi only)
    const long long NEMB = 2LL * VOCAB * EMB;             // emb hi/lo
    const long long NM   = 2LL * NT * NB;
    const long long NH   = 2LL * NB * UNITS;
    const long long NHHF = 2LL * NB * UNITS;              // h fp16 hi (pp=0)
    const long long total = NUH + NWF + NEMB + NM + NH + NHHF;
    const long long stride = (long long)gridDim.x * blockDim.x;
    for (long long i = (long long)blockIdx.x * blockDim.x + threadIdx.x; i < total; i += stride) {
        if (i < NUH) {
            int dir = (int)(i / ((long long)G3 * UNITS));
            long long r2 = i - (long long)dir * G3 * UNITS;
            int p = (int)(r2 / UNITS);
            int k = (int)(r2 % UNITS);
            const float* U = dir ? Ub : Uf;
            g_uh[dir][p][k] = __float2half(U[(long long)k * G3 + (p % 3) * UNITS + p / 3]);
        } else if (i < NUH + NWF) {
            long long j = i - NUH;
            int dir = (int)(j / (16LL * 384 * 32));
            int r = (int)(j % (16LL * 384 * 32));
            int ks = r / (384 * 32); r %= 384 * 32;
            int pt = r / 32;
            int lane = r % 32;
            int gid = lane >> 2, tig = lane & 3;
            int p = pt * 8 + gid;
            const float* W = dir ? Wb : Wf;
            const long long poff = (long long)(p % 3) * UNITS + p / 3;
            int k0 = ks * 16 + 2 * tig;
            unsigned short b0 = hfbits(__float2half(W[(long long)(k0 + 0) * G3 + poff]));
            unsigned short b1 = hfbits(__float2half(W[(long long)(k0 + 1) * G3 + poff]));
            unsigned short b2 = hfbits(__float2half(W[(long long)(k0 + 8) * G3 + poff]));
            unsigned short b3 = hfbits(__float2half(W[(long long)(k0 + 9) * G3 + poff]));
            g_wbfF[j] = (ull)b0 | ((ull)b1 << 16) | ((ull)b2 << 32) | ((ull)b3 << 48);
        } else if (i < NUH + NWF + NEMB) {
            long long j = i - NUH - NWF;
            int sp = (int)(j / ((long long)VOCAB * EMB));
            long long rem = j - (long long)sp * VOCAB * EMB;
            int e = (int)(rem / EMB), c = (int)(rem % EMB);
            float val = emb[(long long)e * EMB + c];
            __half hi = __float2half(val);
            if (sp == 0) g_embh[0][e][c] = hi;
            else         g_embh[1][e][c] = __float2half(val - __half2float(hi));
        } else if (i < NUH + NWF + NEMB + NM) {
            long long j = i - NUH - NWF - NEMB;
            int dir = (int)(j / (NT * NB));
            int rem = (int)(j % (NT * NB));
            int s = rem / NB, b = rem % NB;
            int t = dir ? (NT - 1 - s) : s;
            g_mask[dir][s][b] = (x[b * NT + t] != 0) ? 1 : 0;
        } else if (i < NUH + NWF + NEMB + NM + NH) {
            long long j = i - NUH - NWF - NEMB - NM;
            int dir = (int)(j / (NB * UNITS));
            int rem = (int)(j % (NB * UNITS));
            int b = rem / UNITS, u = rem % UNITS;
            g_h[dir][b][u] = hidden[b * UNITS + u];
        } else {
            long long j = i - NUH - NWF - NEMB - NM - NH;
            int dir = (int)(j / (NB * UNITS));
            int rem = (int)(j % (NB * UNITS));
            int b = rem / UNITS, u = rem % UNITS;
            g_hhf[dir][0][b][u] = __float2half(hidden[b * UNITS + u]);
        }
    }
    if (blockIdx.x == 0 && threadIdx.x == 0) {
        g_bar_count = 0u; g_bar_gen = 0u;
        for (int d = 0; d < 2; d++) {
            g_root[d][0] = 0u; g_gen2[d][0] = 0u;
            for (int l = 0; l < 8; l++) g_leaf[d][l][0] = 0u;
        }
    }
}

// ---------------- gx via HMMA fp16 2-term: C = xe @ W^T (unchanged, proven) ------------
#define GX_SMEM_BYTES (65536 + 512)
__global__ __launch_bounds__(256) void gx_kernel(const int* __restrict__ x,
                                                 const float* __restrict__ bf_in,
                                                 const float* __restrict__ bb_in) {
    extern __shared__ char smx[];
    const uint32_t smb = smem_u32(smx);
    int* toks = (int*)(smx + 65536);

    const int ct  = blockIdx.x;
    const int t   = blockIdx.y;
    const int dir = blockIdx.z;
    const int tid = threadIdx.x;
    const int wid = tid >> 5;
    const int lane = tid & 31;
    const int mi = wid & 3;
    const int nj = wid >> 2;
    const int gid = lane >> 2;
    const int tig = lane & 3;

    if (tid < 64) {
        int tt = dir ? (NT - 1 - t) : t;
        toks[tid] = x[tid * NT + tt];
    }
    __syncthreads();

#pragma unroll
    for (int j = 0; j < 16; j++) {
        int f = tid + j * 256;
        int sp = f >> 11;
        int rem = f & 2047;
        int row = rem >> 5;
        int seg = rem & 31;
        const void* src = &g_embh[sp][toks[row]][seg * 8];
        uint32_t dst = smb + (uint32_t)sp * 32768u + (uint32_t)(row * 512)
                     + (uint32_t)((seg ^ (row & 7)) << 4);
        CP_ASYNC16(dst, src);
    }
    CP_COMMIT();
    CP_WAIT0();
    __syncthreads();

    float c[4][4];
#pragma unroll
    for (int i = 0; i < 4; i++) { c[i][0] = 0.f; c[i][1] = 0.f; c[i][2] = 0.f; c[i][3] = 0.f; }

    const int arow = mi * 16 + (lane & 15);
    const int acb  = lane >> 4;
    const uint32_t abase = smb + (uint32_t)(arow * 512);
    const ull* wf = g_wbfF + (size_t)dir * 16 * 384 * 32;

#pragma unroll
    for (int ks = 0; ks < 16; ks++) {
        const int seg = ks * 2 + acb;
        const uint32_t sw = (uint32_t)((seg ^ (arow & 7)) << 4);
        uint32_t ah0, ah1, ah2, ah3, al0, al1, al2, al3;
        LDMATRIX_X4(ah0, ah1, ah2, ah3, abase + sw);
        LDMATRIX_X4(al0, al1, al2, al3, abase + 32768u + sw);
        ull vh[4];
#pragma unroll
        for (int ntl = 0; ntl < 4; ntl++)
            vh[ntl] = __ldg(wf + ((size_t)ks * 384 + ct * 8 + nj * 4 + ntl) * 32 + lane);
#pragma unroll
        for (int ntl = 0; ntl < 4; ntl++)
            MMA_F16(c[ntl], ah0, ah1, ah2, ah3, (uint32_t)vh[ntl], (uint32_t)(vh[ntl] >> 32));
#pragma unroll
        for (int ntl = 0; ntl < 4; ntl++)
            MMA_F16(c[ntl], al0, al1, al2, al3, (uint32_t)vh[ntl], (uint32_t)(vh[ntl] >> 32));
    }

    __syncthreads();
    float* Cb = (float*)smx;              // [64][68]
    {
        const int r0 = mi * 16 + gid;
#pragma unroll
        for (int ntl = 0; ntl < 4; ntl++) {
            const int col = nj * 32 + ntl * 8 + 2 * tig;
            *(float2*)&Cb[r0 * 68 + col]       = make_float2(c[ntl][0], c[ntl][1]);
            *(float2*)&Cb[(r0 + 8) * 68 + col] = make_float2(c[ntl][2], c[ntl][3]);
        }
    }
    __syncthreads();

    {
        const int b   = tid & 63;
        const int grp = tid >> 6;
        const int pbase = ct * 64;
        const float* bsrc = dir ? bb_in : bf_in;
        float o[16];
#pragma unroll
        for (int q = 0; q < 16; q++) {
            int p = pbase + grp * 16 + q;
            o[q] = Cb[b * 68 + grp * 16 + q] + __ldg(bsrc + (p % 3) * UNITS + p / 3);
        }
        float* gxp = g_gx + ((size_t)(dir * NT + t) * NB + b) * G3 + pbase + grp * 16;
#pragma unroll
        for (int q = 0; q < 4; q++)
            *(float4*)(gxp + q * 4) = *(const float4*)&o[q * 4];
    }
}

// ---------------- persistent HMMA recurrent kernel (1-term fp16, 8 chunks of K=128) ---
// U frags: 98304 B | A: 3 slots x 16384 B (64 rows x 256 B) | bias 192
#define ABUF_OFF    98304u
#define BIAS_OFF    147456u
#define REC_SMEM_BYTES 147648

__global__ __launch_bounds__(256, 1) void recurrent_kernel(const float* __restrict__ bf_rec,
                                                           const float* __restrict__ bb_rec,
                                                           const float* __restrict__ Wp,
                                                           const float* __restrict__ bp,
                                                           float* __restrict__ out) {
    extern __shared__ char smx[];
    const uint32_t smb = smem_u32(smx);

    const int blk   = blockIdx.x;
    const int dir   = blk >> 6;
    const int utile = blk & 63;
    const int pbase = utile * 48;
    const int ubase = utile * 16;
    const int tid  = threadIdx.x;
    const int wid  = tid >> 5;
    const int lane = tid & 31;
    const int mi = wid & 3;
    const int nj = wid >> 2;
    const int gid = lane >> 2;
    const int tig = lane & 3;
    const int leaf = utile >> 3;

    if (tid < 48) {
        const float* brec = dir ? bb_rec : bf_rec;
        ((float*)(smx + BIAS_OFF))[tid] = brec[(tid % 3) * UNITS + ubase + tid / 3];
    }

    // fragment-ordered U (hi only) in smem: [ksg*6 + ntile][lane] x 8B (ksg 0..63)
    for (int e = wid; e < 384; e += 8) {
        int ks = e / 6;
        int nt = e % 6;
        int p  = pbase + nt * 8 + gid;
        const __half* uh = &g_uh[dir][p][ks * 16 + 2 * tig];
        ull v = (ull)(*(const uint32_t*)uh) | ((ull)(*(const uint32_t*)(uh + 8)) << 32);
        *(ull*)(smx + ((size_t)e * 32 + lane) * 8) = v;
    }
    __syncthreads();

    const int b_ep = tid & 63;
    const int usub = tid >> 6;
    const int bar_id = 1 + mi;           // pair barrier id (warps mi and mi+4)

    // per-warp staging: pair covers rows mi*16..+15, 16 segs of 16B per row (K=128)
    const int st_row  = mi * 16 + (lane >> 1);
    const int st_sega = nj * 8 + (lane & 1) * 4;      // segs [st_sega, st_sega+3]
    const uint32_t st_dst_base = smb + ABUF_OFF + (uint32_t)(st_row * 256);

    // h carried in registers across steps
    float hp[4];
    *(float4*)hp = *(const float4*)(&g_h[dir][b_ep][ubase + usub * 4]);

    for (int s = 0; s < NT; s++) {
        const int pp  = s & 1;
        const int ppn = pp ^ 1;

        float gxv[12];
        {
            const float* gxr = g_gx + ((size_t)(dir * NT + s) * NB + b_ep) * G3 + pbase + usub * 12;
#pragma unroll
            for (int q = 0; q < 3; q++)
                *(float4*)&gxv[q * 4] = __ldcs((const float4*)(gxr + q * 4));
        }
        const int m = g_mask[dir][s][b_ep];

        const __half* hsrc = &g_hhf[dir][pp][st_row][0];

        // prologue: stage chunks 0 and 1 (slots 0, 1)
#pragma unroll
        for (int pc = 0; pc < 2; pc++) {
            const uint32_t slot_dst = st_dst_base + (uint32_t)pc * 16384u;
            const __half* src = hsrc + pc * 128;
#pragma unroll
            for (int q = 0; q < 4; q++) {
                int seg = st_sega + q;
                CP_ASYNC16(slot_dst + (uint32_t)((seg ^ (st_row & 7)) * 16),
                           src + seg * 8);
            }
            CP_COMMIT();
        }

        float c[3][4];
#pragma unroll
        for (int i = 0; i < 3; i++) { c[i][0] = 0.f; c[i][1] = 0.f; c[i][2] = 0.f; c[i][3] = 0.f; }

        const int arow = mi * 16 + (lane & 15);
        const int acb  = lane >> 4;

        int slot = 0;                     // ci % 3
        int slot2 = 2;                    // (ci+2) % 3
        for (int ci = 0; ci < 8; ci++) {
            if (ci < 7) CP_WAIT1(); else CP_WAIT0();
            NAMED_BAR(bar_id);           // pair: chunk ci staged, ci-1 consumed
            if (ci < 6) {
                const uint32_t slot_dst = st_dst_base + (uint32_t)slot2 * 16384u;
                const __half* src = hsrc + (ci + 2) * 128;
#pragma unroll
                for (int q = 0; q < 4; q++) {
                    int seg = st_sega + q;
                    CP_ASYNC16(slot_dst + (uint32_t)((seg ^ (st_row & 7)) * 16),
                               src + seg * 8);
                }
                CP_COMMIT();
            }
            const uint32_t abase = smb + ABUF_OFF + (uint32_t)slot * 16384u
                                 + (uint32_t)(arow * 256);
#pragma unroll
            for (int ks = 0; ks < 8; ks++) {
                const int seg = ks * 2 + acb;                  // 0..15
                const uint32_t sw = (uint32_t)((seg ^ (arow & 7)) * 16);
                uint32_t ah0, ah1, ah2, ah3;
                LDMATRIX_X4(ah0, ah1, ah2, ah3, abase + sw);
                const int ksg = ci * 8 + ks;                   // 0..63
                ull vh[3];
#pragma unroll
                for (int ntl = 0; ntl < 3; ntl++)
                    vh[ntl] = *(const ull*)
                        (smx + ((size_t)(ksg * 6 + nj * 3 + ntl) * 32 + lane) * 8);
#pragma unroll
                for (int ntl = 0; ntl < 3; ntl++)
                    MMA_F16(c[ntl], ah0, ah1, ah2, ah3, (uint32_t)vh[ntl], (uint32_t)(vh[ntl] >> 32));
            }
            slot = (slot == 2) ? 0 : slot + 1;
            slot2 = (slot2 == 2) ? 0 : slot2 + 1;
        }

        // redistribute C through smem (block-wide)
        __syncthreads();
        float* Cb = (float*)(smx + ABUF_OFF);
        {
            const int r0 = mi * 16 + gid;
#pragma unroll
            for (int ntl = 0; ntl < 3; ntl++) {
                const int col = nj * 24 + ntl * 8 + 2 * tig;
                *(float2*)&Cb[r0 * 52 + col]       = make_float2(c[ntl][0], c[ntl][1]);
                *(float2*)&Cb[(r0 + 8) * 52 + col] = make_float2(c[ntl][2], c[ntl][3]);
            }
        }
        __syncthreads();

        // GRU epilogue
        {
            float acc[12];
#pragma unroll
            for (int q = 0; q < 3; q++)
                *(float4*)&acc[q * 4] = *(const float4*)&Cb[b_ep * 52 + usub * 12 + q * 4];
            const float* sb = (const float*)(smx + BIAS_OFF) + usub * 12;
            const int tt = dir ? (NT - 1 - s) : s;

            float hn[4];
            __half hi4[4];
#pragma unroll
            for (int ul = 0; ul < 4; ul++) {
                float z = sigmoid_fast(gxv[ul * 3 + 0] + acc[ul * 3 + 0] + sb[ul * 3 + 0]);
                float r = sigmoid_fast(gxv[ul * 3 + 1] + acc[ul * 3 + 1] + sb[ul * 3 + 1]);
                float hh = tanh_fast(gxv[ul * 3 + 2] + r * (acc[ul * 3 + 2] + sb[ul * 3 + 2]));
                float v = z * hp[ul] + (1.f - z) * hh;
                if (!m) v = hp[ul];
                hn[ul] = v;
                hi4[ul] = __float2half(v);
            }
            const int uo = ubase + usub * 4;
            *(float4*)(out + ((size_t)b_ep * NT + tt) * (2 * UNITS) + dir * UNITS + uo)
                = *(const float4*)hn;
            *(uint2*)(&g_hhf[dir][ppn][b_ep][uo]) = *(const uint2*)hi4;
#pragma unroll
            for (int ul = 0; ul < 4; ul++) hp[ul] = hn[ul];
            if (s == NT - 1)
                *(float4*)(&g_h[dir][b_ep][uo]) = *(const float4*)hn;
        }

        barrier_2level(dir, leaf, (unsigned)(s + 1));
    }

    // full barrier before cross-dir final state
    barrier_generic(&g_bar_count, &g_bar_gen, 128u, 1u);

    // fused final state: tanh(concat(hf,hb) @ Wp + bp)
    {
        float* sst = (float*)smx;
        const int tx8 = tid & 7;
        const int tyS = tid >> 3;
        const int b0 = tyS * 2;
        const int ocol = blk * 8 + tx8;
        const float* wp = Wp + ocol;
        float acc0 = 0.f, acc1 = 0.f;
        for (int k0 = 0; k0 < 2 * UNITS; k0 += 128) {
            __syncthreads();
#pragma unroll
            for (int j = 0; j < 8; j++) {
                int f = tid + j * 256;
                int b = f >> 5;
                int k4 = (f & 31) << 2;
                int gk = k0 + k4;
                float4 v = __ldcg((const float4*)(&g_h[gk >> 10][b][gk & 1023]));
                *(float4*)&sst[b * 132 + k4] = v;
            }
            __syncthreads();
#pragma unroll 8
            for (int kk = 0; kk < 128; kk++) {
                float w = __ldg(wp + (size_t)(k0 + kk) * UNITS);
                acc0 = fmaf(sst[b0 * 132 + kk], w, acc0);
                acc1 = fmaf(sst[(b0 + 1) * 132 + kk], w, acc1);
            }
        }
        float bpv = bp[ocol];
        const size_t so = (size_t)NB * NT * (2 * UNITS);
        out[so + (size_t)b0 * UNITS + ocol]       = tanhf(acc0 + bpv);
        out[so + (size_t)(b0 + 1) * UNITS + ocol] = tanhf(acc1 + bpv);
    }
}

// ---------------- launch --------------------------------------------------------------
extern "C" void kernel_launch(void* const* d_in, const int* in_sizes, int n_in,
                              void* d_out, int out_size) {
    (void)in_sizes; (void)n_in; (void)out_size;
    const int*   x      = (const int*)  d_in[0];
    const float* hidden = (const float*)d_in[1];
    const float* emb    = (const float*)d_in[2];
    const float* Wf     = (const float*)d_in[3];
    const float* Uf     = (const float*)d_in[4];
    const float* bf_in  = (const float*)d_in[5];
    const float* bf_rec = (const float*)d_in[6];
    const float* Wb     = (const float*)d_in[7];
    const float* Ub     = (const float*)d_in[8];
    const float* bb_in  = (const float*)d_in[9];
    const float* bb_rec = (const float*)d_in[10];
    const float* Wp     = (const float*)d_in[11];
    const float* bp     = (const float*)d_in[12];
    float* out = (float*)d_out;

    cudaFuncSetAttribute(recurrent_kernel,
                         cudaFuncAttributeMaxDynamicSharedMemorySize, REC_SMEM_BYTES);
    cudaFuncSetAttribute(gx_kernel,
                         cudaFuncAttributeMaxDynamicSharedMemorySize, GX_SMEM_BYTES);

    prep_kernel<<<4096, 256>>>(x, hidden, emb, Wf, Uf, Wb, Ub);
    dim3 ggx(48, NT, 2);
    gx_kernel<<<ggx, 256, GX_SMEM_BYTES>>>(x, bf_in, bb_in);
    recurrent_kernel<<<REC_BLOCKS, 256, REC_SMEM_BYTES>>>(bf_rec, bb_rec, Wp, bp, out);
}